// round 9
// baseline (speedup 1.0000x reference)
#include <cuda_runtime.h>
#include <cuda_bf16.h>
#include <math.h>
#include <stdint.h>

#define NN 50000
#define NE 800000
#define NG 64
#define NC 10
#define CHUNK 1024
#define NCHUNK ((NN + CHUNK - 1) / CHUNK)   // 49

__device__ __forceinline__ uint32_t f2tf32(float x) {
    uint32_t u;
    asm("cvt.rna.tf32.f32 %0, %1;" : "=r"(u) : "f"(x));
    return u;
}
__device__ __forceinline__ uint32_t pack_bf2(float a, float b) {
    __nv_bfloat162 p = __floats2bfloat162_rn(a, b);
    return *(uint32_t*)&p;
}
__device__ __forceinline__ float2 unpack_bf2(uint32_t u) {
    return __bfloat1622float2(*(__nv_bfloat162*)&u);
}

// ---------------- scratch ----------------------------------------------------
__device__ __align__(16) float g_dinv[NN];
__device__ int   g_cnt[NN];
__device__ int   g_rowptr[NN + 1];
__device__ int   g_cursor[NN];
__device__ __align__(16) uint2 g_edge[NE];          // {src, val bits}
__device__ int   g_chunksum[NCHUNK];
__device__ __align__(16) __nv_bfloat16 g_hA[NN * 128];   // layer outputs (<=128 feats)
__device__ __align__(16) __nv_bfloat16 g_hB[NN * 64];
__device__ __align__(16) __nv_bfloat16 g_hO[NN * 256];   // layer-4 output
__device__ __align__(16) float g_Wt3[128 * 64];    // W3^T tf32
__device__ __align__(16) float g_Wt4[256 * 128];   // W4^T tf32
__device__ float g_pool[NG * 256];
__device__ float g_gcnt[NG];

// ---------------- preprocessing ---------------------------------------------
__global__ void init_kernel(const float* __restrict__ W3, const float* __restrict__ W4) {
    int i = blockIdx.x * blockDim.x + threadIdx.x;
    if (i < NN) g_cnt[i] = 0;
    if (i < NG * 256) g_pool[i] = 0.f;
    if (i < NG) g_gcnt[i] = 0.f;
    if (i < 128 * 64) {
        int n = i >> 6, k = i & 63;
        g_Wt3[i] = __uint_as_float(f2tf32(W3[k * 128 + n]));
    }
    if (i < 256 * 128) {
        int n = i >> 7, k = i & 127;
        g_Wt4[i] = __uint_as_float(f2tf32(W4[k * 256 + n]));
    }
}

__global__ void count_kernel(const int* __restrict__ ei) {
    int e = blockIdx.x * blockDim.x + threadIdx.x;
    if (e < NE) atomicAdd(&g_cnt[ei[NE + e]], 1);
}

__global__ void chunkred_kernel() {
    int c = blockIdx.x, tid = threadIdx.x;
    int base = c * CHUNK;
    int s = 0;
    #pragma unroll
    for (int k = 0; k < CHUNK / 256; k++) {
        int idx = base + tid + k * 256;
        if (idx < NN) {
            int v = g_cnt[idx];
            s += v;
            g_dinv[idx] = rsqrtf((float)(v + 1));
        }
    }
    for (int off = 16; off; off >>= 1) s += __shfl_down_sync(~0u, s, off);
    __shared__ int sm[8];
    if ((tid & 31) == 0) sm[tid >> 5] = s;
    __syncthreads();
    if (tid < 8) {
        int t = sm[tid];
        for (int off = 4; off; off >>= 1) t += __shfl_down_sync(0xff, t, off);
        if (tid == 0) g_chunksum[c] = t;
    }
}

__global__ void scan2_kernel() {
    __shared__ int warpsum[32];
    __shared__ int part[2];
    __shared__ int base_s;
    int c = blockIdx.x, tid = threadIdx.x;

    if (tid < 64) {
        int v = (tid < c && tid < NCHUNK) ? g_chunksum[tid] : 0;
        for (int off = 16; off; off >>= 1) v += __shfl_down_sync(~0u, v, off);
        if ((tid & 31) == 0) part[tid >> 5] = v;
    }
    __syncthreads();
    if (tid == 0) base_s = part[0] + part[1];
    __syncthreads();

    int i = c * CHUNK + tid;
    int v = (i < NN) ? g_cnt[i] : 0;
    int lane = tid & 31, w = tid >> 5;
    int incl = v;
    for (int off = 1; off < 32; off <<= 1) {
        int t = __shfl_up_sync(~0u, incl, off);
        if (lane >= off) incl += t;
    }
    if (lane == 31) warpsum[w] = incl;
    __syncthreads();
    if (w == 0) {
        int ws = warpsum[lane];
        for (int off = 1; off < 32; off <<= 1) {
            int t = __shfl_up_sync(~0u, ws, off);
            if (lane >= off) ws += t;
        }
        warpsum[lane] = ws;
    }
    __syncthreads();
    int excl = incl - v + (w > 0 ? warpsum[w - 1] : 0) + base_s;
    if (i < NN) { g_rowptr[i] = excl; g_cursor[i] = excl; }
    if (i == NN - 1) g_rowptr[NN] = excl + v;
}

__global__ void fillg_kernel(const int* __restrict__ ei, const int* __restrict__ bat) {
    int e = blockIdx.x * blockDim.x + threadIdx.x;
    if (e < NE) {
        int s = ei[e];
        int d = ei[NE + e];
        int pos = atomicAdd(&g_cursor[d], 1);
        g_edge[pos] = make_uint2((unsigned)s, __float_as_uint(g_dinv[s] * g_dinv[d]));
    }
    if (e < NN) atomicAdd(&g_gcnt[bat[e]], 1.f);
}

// ---------------- layer 1: fused agg(x)[5] + FFMA gemm -> bf16 [NN][32] -----
__global__ __launch_bounds__(256) void l1_kernel(
    const float* __restrict__ x, const float* __restrict__ W1,
    const float* __restrict__ b1, __nv_bfloat16* __restrict__ out)
{
    // NT=128 nodes, BX=8 (32/4), BY=32, TN=4
    __shared__ float sW[5 * 32];
    __shared__ float sh[128 * 5];
    int tid = threadIdx.y * 8 + threadIdx.x;
    if (tid < 160) sW[tid] = W1[tid];
    int node0 = blockIdx.x * 128;

    for (int i = tid; i < 128 * 5; i += 256) {
        int j = i / 5, f = i - j * 5;
        int nd = node0 + j;
        float acc = 0.f;
        if (nd < NN) {
            float dv = g_dinv[nd];
            acc = dv * dv * __ldg(&x[(size_t)nd * 5 + f]);
            int e = g_rowptr[nd], end = g_rowptr[nd + 1];
            for (; e + 1 < end; e += 2) {
                uint2 e0 = __ldg(&g_edge[e]);
                uint2 e1 = __ldg(&g_edge[e + 1]);
                acc += __uint_as_float(e0.y) * __ldg(&x[(size_t)e0.x * 5 + f])
                     + __uint_as_float(e1.y) * __ldg(&x[(size_t)e1.x * 5 + f]);
            }
            if (e < end) {
                uint2 e0 = __ldg(&g_edge[e]);
                acc += __uint_as_float(e0.y) * __ldg(&x[(size_t)e0.x * 5 + f]);
            }
        }
        sh[i] = acc;
    }
    __syncthreads();

    int fq = threadIdx.x;
    float4 bv = ((const float4*)b1)[fq];
    float acc[4][4];
    #pragma unroll
    for (int j = 0; j < 4; j++) {
        acc[j][0] = bv.x; acc[j][1] = bv.y; acc[j][2] = bv.z; acc[j][3] = bv.w;
    }
    const float* shb = sh + threadIdx.y * 4 * 5;
    #pragma unroll
    for (int k = 0; k < 5; k++) {
        float4 w = ((const float4*)sW)[k * 8 + fq];
        #pragma unroll
        for (int j = 0; j < 4; j++) {
            float hv = shb[j * 5 + k];
            acc[j][0] += w.x * hv; acc[j][1] += w.y * hv;
            acc[j][2] += w.z * hv; acc[j][3] += w.w * hv;
        }
    }
    #pragma unroll
    for (int j = 0; j < 4; j++) {
        int node = node0 + threadIdx.y * 4 + j;
        if (node < NN) {
            uint2 pk;
            pk.x = pack_bf2(fmaxf(acc[j][0], 0.f), fmaxf(acc[j][1], 0.f));
            pk.y = pack_bf2(fmaxf(acc[j][2], 0.f), fmaxf(acc[j][3], 0.f));
            ((uint2*)(out + (size_t)node * 32))[fq] = pk;
        }
    }
}

// ---------------- layer 2: fused agg(bf16)[32] + FFMA gemm -> bf16 [NN][64] -
__global__ __launch_bounds__(256) void l2_kernel(
    const __nv_bfloat16* __restrict__ A, const float* __restrict__ W2,
    const float* __restrict__ b2, __nv_bfloat16* __restrict__ out)
{
    // NT=64 nodes, BX=16, BY=16, TN=4; K=32, F=64
    __shared__ float sW[32 * 64];
    __shared__ float sh[64 * 32];
    int tid = threadIdx.y * 16 + threadIdx.x;
    {
        const float4* Wv = (const float4*)W2;
        float4* sWv = (float4*)sW;
        for (int i = tid; i < 32 * 64 / 4; i += 256) sWv[i] = Wv[i];
    }
    int node0 = blockIdx.x * 64;
    const uint4* Aq = (const uint4*)A;   // [NN][4] chunks of 8 bf16

    {
        int j = tid >> 2, c = tid & 3;   // 64 nodes x 4 chunks
        int nd = node0 + j;
        float acc[8] = {0, 0, 0, 0, 0, 0, 0, 0};
        if (nd < NN) {
            float dv = g_dinv[nd];
            float s = dv * dv;
            uint4 v = __ldg(&Aq[(size_t)nd * 4 + c]);
            const uint32_t* u = (const uint32_t*)&v;
            #pragma unroll
            for (int q = 0; q < 4; q++) {
                float2 fv = unpack_bf2(u[q]);
                acc[2 * q] = s * fv.x; acc[2 * q + 1] = s * fv.y;
            }
            int e = g_rowptr[nd], end = g_rowptr[nd + 1];
            for (; e + 3 < end; e += 4) {
                uint2 e0 = __ldg(&g_edge[e]),     e1 = __ldg(&g_edge[e + 1]);
                uint2 e2 = __ldg(&g_edge[e + 2]), e3 = __ldg(&g_edge[e + 3]);
                uint4 v0 = __ldg(&Aq[(size_t)e0.x * 4 + c]);
                uint4 v1 = __ldg(&Aq[(size_t)e1.x * 4 + c]);
                uint4 v2 = __ldg(&Aq[(size_t)e2.x * 4 + c]);
                uint4 v3 = __ldg(&Aq[(size_t)e3.x * 4 + c]);
                float w0 = __uint_as_float(e0.y), w1 = __uint_as_float(e1.y);
                float w2 = __uint_as_float(e2.y), w3 = __uint_as_float(e3.y);
                const uint32_t* u0 = (const uint32_t*)&v0;
                const uint32_t* u1 = (const uint32_t*)&v1;
                const uint32_t* u2 = (const uint32_t*)&v2;
                const uint32_t* u3 = (const uint32_t*)&v3;
                #pragma unroll
                for (int q = 0; q < 4; q++) {
                    float2 f0 = unpack_bf2(u0[q]), f1 = unpack_bf2(u1[q]);
                    float2 f2 = unpack_bf2(u2[q]), f3 = unpack_bf2(u3[q]);
                    acc[2 * q]     += w0 * f0.x + w1 * f1.x + w2 * f2.x + w3 * f3.x;
                    acc[2 * q + 1] += w0 * f0.y + w1 * f1.y + w2 * f2.y + w3 * f3.y;
                }
            }
            for (; e < end; e++) {
                uint2 e0 = __ldg(&g_edge[e]);
                uint4 v0 = __ldg(&Aq[(size_t)e0.x * 4 + c]);
                float w0 = __uint_as_float(e0.y);
                const uint32_t* u0 = (const uint32_t*)&v0;
                #pragma unroll
                for (int q = 0; q < 4; q++) {
                    float2 f0 = unpack_bf2(u0[q]);
                    acc[2 * q] += w0 * f0.x; acc[2 * q + 1] += w0 * f0.y;
                }
            }
        }
        float* dst = sh + j * 32 + c * 8;
        #pragma unroll
        for (int q = 0; q < 8; q++) dst[q] = acc[q];
    }
    __syncthreads();

    int fq = threadIdx.x;
    float4 bv = ((const float4*)b2)[fq];
    float acc[4][4];
    #pragma unroll
    for (int j = 0; j < 4; j++) {
        acc[j][0] = bv.x; acc[j][1] = bv.y; acc[j][2] = bv.z; acc[j][3] = bv.w;
    }
    const float* shb = sh + threadIdx.y * 4 * 32;
    #pragma unroll 4
    for (int k = 0; k < 32; k++) {
        float4 w = ((const float4*)sW)[k * 16 + fq];
        #pragma unroll
        for (int j = 0; j < 4; j++) {
            float hv = shb[j * 32 + k];
            acc[j][0] += w.x * hv; acc[j][1] += w.y * hv;
            acc[j][2] += w.z * hv; acc[j][3] += w.w * hv;
        }
    }
    #pragma unroll
    for (int j = 0; j < 4; j++) {
        int node = node0 + threadIdx.y * 4 + j;
        if (node < NN) {
            uint2 pk;
            pk.x = pack_bf2(fmaxf(acc[j][0], 0.f), fmaxf(acc[j][1], 0.f));
            pk.y = pack_bf2(fmaxf(acc[j][2], 0.f), fmaxf(acc[j][3], 0.f));
            ((uint2*)(out + (size_t)node * 64))[fq] = pk;
        }
    }
}

// ------- layers 3/4: fused agg(bf16)[K] + tf32 mma -> bf16 [NN][NS] ---------
template <int K, int NS>
__global__ __launch_bounds__(256) void lmma_kernel(
    const __nv_bfloat16* __restrict__ A, const float* __restrict__ Wt,
    const float* __restrict__ bias, __nv_bfloat16* __restrict__ out)
{
    constexpr int AS = K + 4;
    constexpr int KQ = K / 4;
    constexpr int KQ8 = K / 8;
    extern __shared__ float smem[];
    float* sA = smem;             // [128][AS]
    float* sB = smem + 128 * AS;  // [NS][AS]
    int tid = threadIdx.x;
    int node0 = blockIdx.x * 128;

    // stage B (weights, already tf32)
    for (int i = tid; i < NS * KQ; i += 256) {
        int r = i / KQ, kq = i - r * KQ;
        float4 v = __ldg((const float4*)Wt + (size_t)r * KQ + kq);
        *(float4*)(sB + r * AS + kq * 4) = v;
    }
    // stage A by aggregation (bf16 gather, fp32 accumulate, tf32 round)
    const uint4* Aq = (const uint4*)A;
    for (int t = tid; t < 128 * KQ8; t += 256) {
        int j = t / KQ8, c = t - j * KQ8;
        int nd = node0 + j;
        float acc[8] = {0, 0, 0, 0, 0, 0, 0, 0};
        if (nd < NN) {
            float dv = g_dinv[nd];
            float s = dv * dv;
            uint4 v = __ldg(&Aq[(size_t)nd * KQ8 + c]);
            const uint32_t* u = (const uint32_t*)&v;
            #pragma unroll
            for (int q = 0; q < 4; q++) {
                float2 fv = unpack_bf2(u[q]);
                acc[2 * q] = s * fv.x; acc[2 * q + 1] = s * fv.y;
            }
            int e = g_rowptr[nd], end = g_rowptr[nd + 1];
            for (; e + 3 < end; e += 4) {
                uint2 e0 = __ldg(&g_edge[e]),     e1 = __ldg(&g_edge[e + 1]);
                uint2 e2 = __ldg(&g_edge[e + 2]), e3 = __ldg(&g_edge[e + 3]);
                uint4 v0 = __ldg(&Aq[(size_t)e0.x * KQ8 + c]);
                uint4 v1 = __ldg(&Aq[(size_t)e1.x * KQ8 + c]);
                uint4 v2 = __ldg(&Aq[(size_t)e2.x * KQ8 + c]);
                uint4 v3 = __ldg(&Aq[(size_t)e3.x * KQ8 + c]);
                float w0 = __uint_as_float(e0.y), w1 = __uint_as_float(e1.y);
                float w2 = __uint_as_float(e2.y), w3 = __uint_as_float(e3.y);
                const uint32_t* u0 = (const uint32_t*)&v0;
                const uint32_t* u1 = (const uint32_t*)&v1;
                const uint32_t* u2 = (const uint32_t*)&v2;
                const uint32_t* u3 = (const uint32_t*)&v3;
                #pragma unroll
                for (int q = 0; q < 4; q++) {
                    float2 f0 = unpack_bf2(u0[q]), f1 = unpack_bf2(u1[q]);
                    float2 f2 = unpack_bf2(u2[q]), f3 = unpack_bf2(u3[q]);
                    acc[2 * q]     += w0 * f0.x + w1 * f1.x + w2 * f2.x + w3 * f3.x;
                    acc[2 * q + 1] += w0 * f0.y + w1 * f1.y + w2 * f2.y + w3 * f3.y;
                }
            }
            for (; e < end; e++) {
                uint2 e0 = __ldg(&g_edge[e]);
                uint4 v0 = __ldg(&Aq[(size_t)e0.x * KQ8 + c]);
                float w0 = __uint_as_float(e0.y);
                const uint32_t* u0 = (const uint32_t*)&v0;
                #pragma unroll
                for (int q = 0; q < 4; q++) {
                    float2 f0 = unpack_bf2(u0[q]);
                    acc[2 * q] += w0 * f0.x; acc[2 * q + 1] += w0 * f0.y;
                }
            }
        }
        float* dst = sA + j * AS + c * 8;
        #pragma unroll
        for (int q = 0; q < 8; q++) dst[q] = __uint_as_float(f2tf32(acc[q]));
    }
    __syncthreads();

    int warp = tid >> 5, lane = tid & 31;
    int g = lane >> 2, tg = lane & 3;
    int mrow = warp * 16;

    uint32_t a[K / 8][4];
    #pragma unroll
    for (int kk = 0; kk < K / 8; kk++) {
        const float* p0 = sA + (mrow + g) * AS + kk * 8 + tg;
        const float* p1 = sA + (mrow + g + 8) * AS + kk * 8 + tg;
        a[kk][0] = __float_as_uint(p0[0]);
        a[kk][1] = __float_as_uint(p1[0]);
        a[kk][2] = __float_as_uint(p0[4]);
        a[kk][3] = __float_as_uint(p1[4]);
    }

    int row0 = node0 + mrow + g;
    int row1 = row0 + 8;
    #pragma unroll 2
    for (int ng = 0; ng < NS / 8; ng++) {
        float d0 = 0.f, d1 = 0.f, d2 = 0.f, d3 = 0.f;
        const float* bp = sB + (ng * 8 + g) * AS + tg;
        #pragma unroll
        for (int kk = 0; kk < K / 8; kk++) {
            uint32_t b0 = __float_as_uint(bp[kk * 8]);
            uint32_t b1 = __float_as_uint(bp[kk * 8 + 4]);
            asm volatile(
                "mma.sync.aligned.m16n8k8.row.col.f32.tf32.tf32.f32 "
                "{%0,%1,%2,%3}, {%4,%5,%6,%7}, {%8,%9}, {%0,%1,%2,%3};"
                : "+f"(d0), "+f"(d1), "+f"(d2), "+f"(d3)
                : "r"(a[kk][0]), "r"(a[kk][1]), "r"(a[kk][2]), "r"(a[kk][3]),
                  "r"(b0), "r"(b1));
        }
        int col = ng * 8 + 2 * tg;
        float2 bs = __ldg((const float2*)&bias[col]);
        if (row0 < NN)
            *(uint32_t*)(out + (size_t)row0 * NS + col) =
                pack_bf2(fmaxf(d0 + bs.x, 0.f), fmaxf(d1 + bs.y, 0.f));
        if (row1 < NN)
            *(uint32_t*)(out + (size_t)row1 * NS + col) =
                pack_bf2(fmaxf(d2 + bs.x, 0.f), fmaxf(d3 + bs.y, 0.f));
    }
}

// ---------------- mean-pool (bf16 in) + head --------------------------------
__global__ void poolb_kernel(const __nv_bfloat16* __restrict__ h,
                             const int* __restrict__ batch) {
    const int CH = 64;
    int f = threadIdx.x;
    int n0 = blockIdx.x * CH;
    float acc = 0.f;
    int curg = -1;
    for (int i = 0; i < CH; i++) {
        int nd = n0 + i;
        if (nd >= NN) break;
        int g = batch[nd];
        if (g != curg) {
            if (curg >= 0) atomicAdd(&g_pool[curg * 256 + f], acc);
            acc = 0.f; curg = g;
        }
        acc += __bfloat162float(h[(size_t)nd * 256 + f]);
    }
    if (curg >= 0) atomicAdd(&g_pool[curg * 256 + f], acc);
}

__global__ void head_kernel(const float* __restrict__ fcW, const float* __restrict__ fcb,
                            float* __restrict__ out) {
    __shared__ float slog[NG * NC];
    int tid = threadIdx.x;
    if (tid < NG * NC) {
        int g = tid / NC, c = tid % NC;
        float inv = 1.f / fmaxf(g_gcnt[g], 1.f);
        float a = fcb[c];
        for (int k = 0; k < 256; k++)
            a += g_pool[g * 256 + k] * inv * fcW[k * NC + c];
        slog[tid] = a;
    }
    __syncthreads();
    if (tid < NG * NC) {
        int g = tid / NC;
        float m = -1e30f;
        for (int i = 0; i < NC; i++) m = fmaxf(m, slog[g * NC + i]);
        float s = 0.f;
        for (int i = 0; i < NC; i++) s += expf(slog[g * NC + i] - m);
        out[tid] = slog[tid] - m - logf(s);
    }
}

// ---------------- launch -----------------------------------------------------
extern "C" void kernel_launch(void* const* d_in, const int* in_sizes, int n_in,
                              void* d_out, int out_size) {
    const float* x   = (const float*)d_in[0];
    const int*   ei  = (const int*)d_in[1];
    const int*   bat = (const int*)d_in[2];
    const float* W1 = (const float*)d_in[3];
    const float* b1 = (const float*)d_in[4];
    const float* W2 = (const float*)d_in[5];
    const float* b2 = (const float*)d_in[6];
    const float* W3 = (const float*)d_in[7];
    const float* b3 = (const float*)d_in[8];
    const float* W4 = (const float*)d_in[9];
    const float* b4 = (const float*)d_in[10];
    const float* fcW = (const float*)d_in[11];
    const float* fcb = (const float*)d_in[12];
    float* out = (float*)d_out;

    __nv_bfloat16 *hA, *hB, *hO;
    float *Wt3, *Wt4;
    cudaGetSymbolAddress((void**)&hA, g_hA);
    cudaGetSymbolAddress((void**)&hB, g_hB);
    cudaGetSymbolAddress((void**)&hO, g_hO);
    cudaGetSymbolAddress((void**)&Wt3, g_Wt3);
    cudaGetSymbolAddress((void**)&Wt4, g_Wt4);

    const int smL3 = (128 * (64 + 4) + 128 * (64 + 4)) * 4;      // 69632
    const int smL4 = (128 * (128 + 4) + 256 * (128 + 4)) * 4;    // 202752
    cudaFuncSetAttribute(lmma_kernel<64, 128>,
                         cudaFuncAttributeMaxDynamicSharedMemorySize, smL3);
    cudaFuncSetAttribute(lmma_kernel<128, 256>,
                         cudaFuncAttributeMaxDynamicSharedMemorySize, smL4);

    const int EB = (NE + 255) / 256;
    const int NB = (NN + 255) / 256;

    init_kernel<<<NB, 256>>>(W3, W4);
    count_kernel<<<EB, 256>>>(ei);
    chunkred_kernel<<<NCHUNK, 256>>>();
    scan2_kernel<<<NCHUNK, 1024>>>();
    fillg_kernel<<<EB, 256>>>(ei, bat);

    l1_kernel<<<(NN + 127) / 128, dim3(8, 32)>>>(x, W1, b1, hA);          // [NN][32]
    l2_kernel<<<(NN + 63) / 64, dim3(16, 16)>>>(hA, W2, b2, hB);          // [NN][64]
    lmma_kernel<64, 128><<<(NN + 127) / 128, 256, smL3>>>(hB, Wt3, b3, hA);  // [NN][128]
    lmma_kernel<128, 256><<<(NN + 127) / 128, 256, smL4>>>(hA, Wt4, b4, hO); // [NN][256]

    poolb_kernel<<<(NN + 63) / 64, 256>>>(hO, bat);
    head_kernel<<<1, 640>>>(fcW, fcb, out);

    (void)in_sizes; (void)n_in; (void)out_size;
}

// round 10
// speedup vs baseline: 1.1517x; 1.1517x over previous
#include <cuda_runtime.h>
#include <cuda_bf16.h>
#include <math.h>
#include <stdint.h>

#define NN 50000
#define NE 800000
#define NG 64
#define NC 10
#define CHUNK 1024
#define NCHUNK ((NN + CHUNK - 1) / CHUNK)   // 49

__device__ __forceinline__ uint32_t f2tf32(float x) {
    uint32_t u;
    asm("cvt.rna.tf32.f32 %0, %1;" : "=r"(u) : "f"(x));
    return u;
}
__device__ __forceinline__ uint32_t pack_bf2(float a, float b) {
    __nv_bfloat162 p = __floats2bfloat162_rn(a, b);
    return *(uint32_t*)&p;
}
__device__ __forceinline__ float2 unpack_bf2(uint32_t u) {
    return __bfloat1622float2(*(__nv_bfloat162*)&u);
}

// ---------------- scratch ----------------------------------------------------
__device__ __align__(16) float g_dinv[NN];
__device__ int   g_cnt[NN];
__device__ int   g_rowptr[NN + 1];
__device__ int   g_cursor[NN];
__device__ __align__(16) uint2 g_edge[NE];          // {src, val bits}
__device__ int   g_chunksum[NCHUNK];
__device__ __align__(16) float g_bufT[NN * 8];
__device__ __align__(16) __nv_bfloat16 g_b16A[NN * 128];
__device__ __align__(16) __nv_bfloat16 g_b16B[NN * 128];
__device__ __align__(16) __nv_bfloat16 g_hO[NN * 256];
__device__ __align__(16) float g_Wt3[128 * 64];    // W3^T, tf32-rounded
__device__ __align__(16) float g_Wt4[256 * 128];   // W4^T, tf32-rounded
__device__ float g_pool[NG * 256];
__device__ float g_gcnt[NG];

// ---------------- init: zero + weight transpose/round -----------------------
__global__ void init_kernel(const float* __restrict__ W3, const float* __restrict__ W4) {
    int i = blockIdx.x * blockDim.x + threadIdx.x;
    if (i < NN) g_cnt[i] = 0;
    if (i < NG * 256) g_pool[i] = 0.f;
    if (i < NG) g_gcnt[i] = 0.f;
    if (i < 128 * 64) {
        int n = i >> 6, k = i & 63;
        g_Wt3[i] = __uint_as_float(f2tf32(W3[k * 128 + n]));
    }
    if (i < 256 * 128) {
        int n = i >> 7, k = i & 127;
        g_Wt4[i] = __uint_as_float(f2tf32(W4[k * 256 + n]));
    }
}

__global__ void count_kernel(const int* __restrict__ ei) {
    int e = blockIdx.x * blockDim.x + threadIdx.x;
    if (e < NE) atomicAdd(&g_cnt[ei[NE + e]], 1);
}

__global__ void chunkred_kernel() {
    int c = blockIdx.x, tid = threadIdx.x;
    int base = c * CHUNK;
    int s = 0;
    #pragma unroll
    for (int k = 0; k < CHUNK / 256; k++) {
        int idx = base + tid + k * 256;
        if (idx < NN) {
            int v = g_cnt[idx];
            s += v;
            g_dinv[idx] = rsqrtf((float)(v + 1));
        }
    }
    for (int off = 16; off; off >>= 1) s += __shfl_down_sync(~0u, s, off);
    __shared__ int sm[8];
    if ((tid & 31) == 0) sm[tid >> 5] = s;
    __syncthreads();
    if (tid < 8) {
        int t = sm[tid];
        for (int off = 4; off; off >>= 1) t += __shfl_down_sync(0xff, t, off);
        if (tid == 0) g_chunksum[c] = t;
    }
}

__global__ void scan2_kernel() {
    __shared__ int warpsum[32];
    __shared__ int part[2];
    __shared__ int base_s;
    int c = blockIdx.x, tid = threadIdx.x;

    if (tid < 64) {
        int v = (tid < c && tid < NCHUNK) ? g_chunksum[tid] : 0;
        for (int off = 16; off; off >>= 1) v += __shfl_down_sync(~0u, v, off);
        if ((tid & 31) == 0) part[tid >> 5] = v;
    }
    __syncthreads();
    if (tid == 0) base_s = part[0] + part[1];
    __syncthreads();

    int i = c * CHUNK + tid;
    int v = (i < NN) ? g_cnt[i] : 0;
    int lane = tid & 31, w = tid >> 5;
    int incl = v;
    for (int off = 1; off < 32; off <<= 1) {
        int t = __shfl_up_sync(~0u, incl, off);
        if (lane >= off) incl += t;
    }
    if (lane == 31) warpsum[w] = incl;
    __syncthreads();
    if (w == 0) {
        int ws = warpsum[lane];
        for (int off = 1; off < 32; off <<= 1) {
            int t = __shfl_up_sync(~0u, ws, off);
            if (lane >= off) ws += t;
        }
        warpsum[lane] = ws;
    }
    __syncthreads();
    int excl = incl - v + (w > 0 ? warpsum[w - 1] : 0) + base_s;
    if (i < NN) { g_rowptr[i] = excl; g_cursor[i] = excl; }
    if (i == NN - 1) g_rowptr[NN] = excl + v;
}

__global__ void fillg_kernel(const int* __restrict__ ei, const int* __restrict__ bat) {
    int e = blockIdx.x * blockDim.x + threadIdx.x;
    if (e < NE) {
        int s = ei[e];
        int d = ei[NE + e];
        int pos = atomicAdd(&g_cursor[d], 1);
        g_edge[pos] = make_uint2((unsigned)s, __float_as_uint(g_dinv[s] * g_dinv[d]));
    }
    if (e < NN) atomicAdd(&g_gcnt[bat[e]], 1.f);
}

// ---------------- aggregation ------------------------------------------------
// f32 scalar (layer 1 only, F=5)
template <int F>
__global__ void agg_kernel(const float* __restrict__ h, float* __restrict__ out) {
    int node = blockIdx.x * blockDim.y + threadIdx.y;
    if (node >= NN) return;
    int f = threadIdx.x;
    float dv = g_dinv[node];
    float acc = dv * dv * __ldg(&h[node * F + f]);
    int e = g_rowptr[node], end = g_rowptr[node + 1];
    for (; e + 1 < end; e += 2) {
        uint2 e0 = __ldg(&g_edge[e]);
        uint2 e1 = __ldg(&g_edge[e + 1]);
        acc += __uint_as_float(e0.y) * __ldg(&h[(size_t)e0.x * F + f])
             + __uint_as_float(e1.y) * __ldg(&h[(size_t)e1.x * F + f]);
    }
    if (e < end) {
        uint2 e0 = __ldg(&g_edge[e]);
        acc += __uint_as_float(e0.y) * __ldg(&h[(size_t)e0.x * F + f]);
    }
    out[node * F + f] = acc;
}

// bf16 in -> bf16 out, fp32 accumulate. threads.x = F/8 (one uint4 per thread)
template <int F>
__global__ void aggb_kernel(const uint4* __restrict__ h, uint4* __restrict__ out) {
    constexpr int FQ8 = F / 8;
    int node = blockIdx.x * blockDim.y + threadIdx.y;
    if (node >= NN) return;
    int f = threadIdx.x;
    float dv = g_dinv[node];
    float s = dv * dv;
    float acc[8];
    {
        uint4 v = __ldg(&h[(size_t)node * FQ8 + f]);
        const uint32_t* u = (const uint32_t*)&v;
        #pragma unroll
        for (int j = 0; j < 4; j++) {
            float2 fv = unpack_bf2(u[j]);
            acc[2 * j] = s * fv.x; acc[2 * j + 1] = s * fv.y;
        }
    }
    int e = g_rowptr[node], end = g_rowptr[node + 1];
    for (; e + 3 < end; e += 4) {
        uint2 e0 = __ldg(&g_edge[e]),     e1 = __ldg(&g_edge[e + 1]);
        uint2 e2 = __ldg(&g_edge[e + 2]), e3 = __ldg(&g_edge[e + 3]);
        uint4 v0 = __ldg(&h[(size_t)e0.x * FQ8 + f]);
        uint4 v1 = __ldg(&h[(size_t)e1.x * FQ8 + f]);
        uint4 v2 = __ldg(&h[(size_t)e2.x * FQ8 + f]);
        uint4 v3 = __ldg(&h[(size_t)e3.x * FQ8 + f]);
        float w0 = __uint_as_float(e0.y), w1 = __uint_as_float(e1.y);
        float w2 = __uint_as_float(e2.y), w3 = __uint_as_float(e3.y);
        const uint32_t* u0 = (const uint32_t*)&v0;
        const uint32_t* u1 = (const uint32_t*)&v1;
        const uint32_t* u2 = (const uint32_t*)&v2;
        const uint32_t* u3 = (const uint32_t*)&v3;
        #pragma unroll
        for (int j = 0; j < 4; j++) {
            float2 f0 = unpack_bf2(u0[j]);
            float2 f1 = unpack_bf2(u1[j]);
            float2 f2 = unpack_bf2(u2[j]);
            float2 f3 = unpack_bf2(u3[j]);
            acc[2 * j]     += w0 * f0.x + w1 * f1.x + w2 * f2.x + w3 * f3.x;
            acc[2 * j + 1] += w0 * f0.y + w1 * f1.y + w2 * f2.y + w3 * f3.y;
        }
    }
    for (; e < end; e++) {
        uint2 e0 = __ldg(&g_edge[e]);
        uint4 v0 = __ldg(&h[(size_t)e0.x * FQ8 + f]);
        float w0 = __uint_as_float(e0.y);
        const uint32_t* u0 = (const uint32_t*)&v0;
        #pragma unroll
        for (int j = 0; j < 4; j++) {
            float2 f0 = unpack_bf2(u0[j]);
            acc[2 * j] += w0 * f0.x; acc[2 * j + 1] += w0 * f0.y;
        }
    }
    uint32_t pk[4];
    #pragma unroll
    for (int j = 0; j < 4; j++) pk[j] = pack_bf2(acc[2 * j], acc[2 * j + 1]);
    out[(size_t)node * FQ8 + f] = *(uint4*)pk;
}

// ---------------- tf32 tensor-core GEMM: out = relu(A @ W^T + b) ------------
// A: [NN][K] bf16, Wt: [NTOT][K] tf32-in-f32, out bf16.
template <int K, int NTOT>
__global__ __launch_bounds__(256) void mma_tf32_kernel(
    const __nv_bfloat16* __restrict__ A, const float* __restrict__ Wt,
    const float* __restrict__ bias, __nv_bfloat16* __restrict__ out)
{
    constexpr int AS = K + 4;
    constexpr int NS = 128;
    constexpr int KQ = K / 4;
    constexpr int KQ8 = K / 8;
    extern __shared__ float smem[];
    float* sA = smem;
    float* sB = smem + 128 * AS;
    int tid = threadIdx.x;
    int node0 = blockIdx.x * 128;
    int n0 = blockIdx.y * NS;

    const uint4* Ab = (const uint4*)A;
    for (int i = tid; i < 128 * KQ8; i += 256) {
        int r = i / KQ8, c = i - r * KQ8;
        int nd = node0 + r;
        uint4 v = make_uint4(0, 0, 0, 0);
        if (nd < NN) v = __ldg(&Ab[(size_t)nd * KQ8 + c]);
        const uint32_t* u = (const uint32_t*)&v;
        float* dst = sA + r * AS + c * 8;
        #pragma unroll
        for (int j = 0; j < 4; j++) {
            float2 fv = unpack_bf2(u[j]);
            dst[2 * j] = fv.x; dst[2 * j + 1] = fv.y;
        }
    }
    for (int i = tid; i < NS * KQ; i += 256) {
        int r = i / KQ, kq = i - r * KQ;
        float4 v = __ldg((const float4*)Wt + (size_t)(n0 + r) * KQ + kq);
        *(float4*)(sB + r * AS + kq * 4) = v;
    }
    __syncthreads();

    int warp = tid >> 5, lane = tid & 31;
    int g = lane >> 2, tg = lane & 3;
    int mrow = warp * 16;

    uint32_t a[K / 8][4];
    #pragma unroll
    for (int kk = 0; kk < K / 8; kk++) {
        const float* p0 = sA + (mrow + g) * AS + kk * 8 + tg;
        const float* p1 = sA + (mrow + g + 8) * AS + kk * 8 + tg;
        a[kk][0] = __float_as_uint(p0[0]);
        a[kk][1] = __float_as_uint(p1[0]);
        a[kk][2] = __float_as_uint(p0[4]);
        a[kk][3] = __float_as_uint(p1[4]);
    }

    int row0 = node0 + mrow + g;
    int row1 = row0 + 8;
    #pragma unroll 2
    for (int ng = 0; ng < NS / 8; ng++) {
        float d0 = 0.f, d1 = 0.f, d2 = 0.f, d3 = 0.f;
        const float* bp = sB + (ng * 8 + g) * AS + tg;
        #pragma unroll
        for (int kk = 0; kk < K / 8; kk++) {
            uint32_t b0 = __float_as_uint(bp[kk * 8]);
            uint32_t b1 = __float_as_uint(bp[kk * 8 + 4]);
            asm volatile(
                "mma.sync.aligned.m16n8k8.row.col.f32.tf32.tf32.f32 "
                "{%0,%1,%2,%3}, {%4,%5,%6,%7}, {%8,%9}, {%0,%1,%2,%3};"
                : "+f"(d0), "+f"(d1), "+f"(d2), "+f"(d3)
                : "r"(a[kk][0]), "r"(a[kk][1]), "r"(a[kk][2]), "r"(a[kk][3]),
                  "r"(b0), "r"(b1));
        }
        int col = n0 + ng * 8 + 2 * tg;
        float2 bs = __ldg((const float2*)&bias[col]);
        if (row0 < NN)
            *(uint32_t*)(out + (size_t)row0 * NTOT + col) =
                pack_bf2(fmaxf(d0 + bs.x, 0.f), fmaxf(d1 + bs.y, 0.f));
        if (row1 < NN)
            *(uint32_t*)(out + (size_t)row1 * NTOT + col) =
                pack_bf2(fmaxf(d2 + bs.x, 0.f), fmaxf(d3 + bs.y, 0.f));
    }
}

// ---------------- dense FFMA (layers 1-2): out = relu(in @ W + b) -----------
// INB: input bf16; output always bf16.
template <int K, int F, int TN, int INB>
__global__ __launch_bounds__(256) void gemm_relu_kernel(
    const void* __restrict__ inp, const float* __restrict__ W,
    const float* __restrict__ bias, __nv_bfloat16* __restrict__ outp)
{
    constexpr int TF = 4;
    constexpr int BX = F / TF;
    constexpr int BY = 256 / BX;
    constexpr int NT = TN * BY;
    constexpr int NTILES = (NN + NT - 1) / NT;
    extern __shared__ float fsm[];
    float* sW = fsm;
    float* sh = fsm + K * F;
    int tid = threadIdx.y * BX + threadIdx.x;

    const float4* Wv = (const float4*)W;
    float4* sWv = (float4*)sW;
    for (int i = tid; i < K * F / 4; i += 256) sWv[i] = Wv[i];

    int fq = threadIdx.x;
    float4 bv = ((const float4*)bias)[fq];

    for (int tile = blockIdx.x; tile < NTILES; tile += gridDim.x) {
        int node0 = tile * NT;
        __syncthreads();
        if constexpr (INB) {
            constexpr int KQ = K / 4;
            const uint2* inb = (const uint2*)inp;
            for (int i = tid; i < NT * KQ; i += 256) {
                int j = i / KQ, kq = i - j * KQ;
                int nd = node0 + j;
                uint2 v = make_uint2(0, 0);
                if (nd < NN) v = __ldg(&inb[(size_t)nd * KQ + kq]);
                float2 f0 = unpack_bf2(v.x), f1 = unpack_bf2(v.y);
                float* d = sh + j * K + kq * 4;
                d[0] = f0.x; d[1] = f0.y; d[2] = f1.x; d[3] = f1.y;
            }
        } else {
            const float* in = (const float*)inp;
            for (int i = tid; i < NT * K; i += 256) {
                int j = i / K, k = i - j * K;
                int nd = node0 + j;
                sh[i] = (nd < NN) ? in[(size_t)nd * K + k] : 0.f;
            }
        }
        __syncthreads();

        float acc[TN][4];
        #pragma unroll
        for (int j = 0; j < TN; j++) {
            acc[j][0] = bv.x; acc[j][1] = bv.y; acc[j][2] = bv.z; acc[j][3] = bv.w;
        }
        const float* shb = sh + threadIdx.y * TN * K;
        #pragma unroll 4
        for (int k = 0; k < K; k++) {
            float4 w = ((const float4*)sW)[k * BX + fq];
            #pragma unroll
            for (int j = 0; j < TN; j++) {
                float hv = shb[j * K + k];
                acc[j][0] += w.x * hv;
                acc[j][1] += w.y * hv;
                acc[j][2] += w.z * hv;
                acc[j][3] += w.w * hv;
            }
        }
        #pragma unroll
        for (int j = 0; j < TN; j++) {
            int node = node0 + threadIdx.y * TN + j;
            if (node < NN) {
                uint2 pk;
                pk.x = pack_bf2(fmaxf(acc[j][0], 0.f), fmaxf(acc[j][1], 0.f));
                pk.y = pack_bf2(fmaxf(acc[j][2], 0.f), fmaxf(acc[j][3], 0.f));
                ((uint2*)(outp + (size_t)node * F))[fq] = pk;
            }
        }
    }
}

// ---------------- mean-pool (bf16 in) + head --------------------------------
__global__ void poolb_kernel(const __nv_bfloat16* __restrict__ h,
                             const int* __restrict__ batch) {
    const int CH = 64;
    int f = threadIdx.x;
    int n0 = blockIdx.x * CH;
    float acc = 0.f;
    int curg = -1;
    for (int i = 0; i < CH; i++) {
        int nd = n0 + i;
        if (nd >= NN) break;
        int g = batch[nd];
        if (g != curg) {
            if (curg >= 0) atomicAdd(&g_pool[curg * 256 + f], acc);
            acc = 0.f; curg = g;
        }
        acc += __bfloat162float(h[(size_t)nd * 256 + f]);
    }
    if (curg >= 0) atomicAdd(&g_pool[curg * 256 + f], acc);
}

__global__ void head_kernel(const float* __restrict__ fcW, const float* __restrict__ fcb,
                            float* __restrict__ out) {
    __shared__ float slog[NG * NC];
    int tid = threadIdx.x;
    if (tid < NG * NC) {
        int g = tid / NC, c = tid % NC;
        float inv = 1.f / fmaxf(g_gcnt[g], 1.f);
        float a = fcb[c];
        for (int k = 0; k < 256; k++)
            a += g_pool[g * 256 + k] * inv * fcW[k * NC + c];
        slog[tid] = a;
    }
    __syncthreads();
    if (tid < NG * NC) {
        int g = tid / NC;
        float m = -1e30f;
        for (int i = 0; i < NC; i++) m = fmaxf(m, slog[g * NC + i]);
        float s = 0.f;
        for (int i = 0; i < NC; i++) s += expf(slog[g * NC + i] - m);
        out[tid] = slog[tid] - m - logf(s);
    }
}

// ---------------- launch -----------------------------------------------------
extern "C" void kernel_launch(void* const* d_in, const int* in_sizes, int n_in,
                              void* d_out, int out_size) {
    const float* x   = (const float*)d_in[0];
    const int*   ei  = (const int*)d_in[1];
    const int*   bat = (const int*)d_in[2];
    const float* W1 = (const float*)d_in[3];
    const float* b1 = (const float*)d_in[4];
    const float* W2 = (const float*)d_in[5];
    const float* b2 = (const float*)d_in[6];
    const float* W3 = (const float*)d_in[7];
    const float* b3 = (const float*)d_in[8];
    const float* W4 = (const float*)d_in[9];
    const float* b4 = (const float*)d_in[10];
    const float* fcW = (const float*)d_in[11];
    const float* fcb = (const float*)d_in[12];
    float* out = (float*)d_out;

    float *bufT, *Wt3, *Wt4;
    __nv_bfloat16 *bA, *bB, *hO;
    cudaGetSymbolAddress((void**)&bufT, g_bufT);
    cudaGetSymbolAddress((void**)&bA, g_b16A);
    cudaGetSymbolAddress((void**)&bB, g_b16B);
    cudaGetSymbolAddress((void**)&hO, g_hO);
    cudaGetSymbolAddress((void**)&Wt3, g_Wt3);
    cudaGetSymbolAddress((void**)&Wt4, g_Wt4);

    const int smL3 = (128 * (64 + 4) + 128 * (64 + 4)) * 4;     // 69632
    const int smL4 = (128 * (128 + 4) + 128 * (128 + 4)) * 4;   // 135168
    cudaFuncSetAttribute(mma_tf32_kernel<64, 128>,
                         cudaFuncAttributeMaxDynamicSharedMemorySize, smL3);
    cudaFuncSetAttribute(mma_tf32_kernel<128, 256>,
                         cudaFuncAttributeMaxDynamicSharedMemorySize, smL4);

    const int EB = (NE + 255) / 256;
    const int NB = (NN + 255) / 256;

    init_kernel<<<NB, 256>>>(W3, W4);
    count_kernel<<<EB, 256>>>(ei);
    chunkred_kernel<<<NCHUNK, 256>>>();
    scan2_kernel<<<NCHUNK, 1024>>>();
    fillg_kernel<<<EB, 256>>>(ei, bat);

    // layer 1: agg(x f32)[5] -> FFMA gemm -> bA bf16 [NN][32]
    {
        dim3 blk(5, 51);
        agg_kernel<5><<<(NN + 50) / 51, blk>>>(x, bufT);
        int smem = (5 * 32 + 128 * 5) * 4;
        gemm_relu_kernel<5, 32, 4, 0><<<391, dim3(8, 32), smem>>>(bufT, W1, b1, bA);
    }
    // layer 2: aggb(bA)[32] -> bB; FFMA gemm (bf16 in) -> bA bf16 [NN][64]
    {
        dim3 blk(4, 64);
        aggb_kernel<32><<<(NN + 63) / 64, blk>>>((const uint4*)bA, (uint4*)bB);
        int smem = (32 * 64 + 64 * 32) * 4;
        gemm_relu_kernel<32, 64, 4, 1><<<592, dim3(16, 16), smem>>>(bB, W2, b2, bA);
    }
    // layer 3: aggb(bA)[64] -> bB; tf32 mma -> bA bf16 [NN][128]
    {
        dim3 blk(8, 32);
        aggb_kernel<64><<<(NN + 31) / 32, blk>>>((const uint4*)bA, (uint4*)bB);
        mma_tf32_kernel<64, 128><<<dim3(391, 1), 256, smL3>>>(bB, Wt3, b3, bA);
    }
    // layer 4: aggb(bA)[128] -> bB; tf32 mma -> hO bf16 [NN][256]
    {
        dim3 blk(16, 16);
        aggb_kernel<128><<<(NN + 15) / 16, blk>>>((const uint4*)bA, (uint4*)bB);
        mma_tf32_kernel<128, 256><<<dim3(391, 2), 256, smL4>>>(bB, Wt4, b4, hO);
    }

    // mean pool + head
    poolb_kernel<<<(NN + 63) / 64, 256>>>(hO, bat);
    head_kernel<<<1, 640>>>(fcW, fcb, out);

    (void)in_sizes; (void)n_in; (void)out_size;
}

// round 11
// speedup vs baseline: 1.2183x; 1.0578x over previous
#include <cuda_runtime.h>
#include <cuda_bf16.h>
#include <math.h>
#include <stdint.h>

#define NN 50000
#define NE 800000
#define NG 64
#define NC 10
#define CHUNK 1024
#define NCHUNK ((NN + CHUNK - 1) / CHUNK)   // 49

__device__ __forceinline__ uint32_t f2tf32(float x) {
    uint32_t u;
    asm("cvt.rna.tf32.f32 %0, %1;" : "=r"(u) : "f"(x));
    return u;
}
__device__ __forceinline__ uint32_t pack_bf2(float a, float b) {
    __nv_bfloat162 p = __floats2bfloat162_rn(a, b);
    return *(uint32_t*)&p;
}
__device__ __forceinline__ float2 unpack_bf2(uint32_t u) {
    return __bfloat1622float2(*(__nv_bfloat162*)&u);
}

// ---------------- scratch ----------------------------------------------------
__device__ __align__(16) float g_dinv[NN];
__device__ int   g_cnt[NN];
__device__ int   g_rowptr[NN + 1];
__device__ int   g_cursor[NN];
__device__ __align__(16) int g_col[NE];
__device__ int   g_chunksum[NCHUNK];
__device__ __align__(16) __nv_bfloat16 g_zx[NN * 8];     // dinv*x, bf16, padded
__device__ __align__(16) __nv_bfloat16 g_b16A[NN * 128];
__device__ __align__(16) __nv_bfloat16 g_b16B[NN * 128];
__device__ __align__(16) __nv_bfloat16 g_hO[NN * 256];
__device__ __align__(16) float g_Wt1[32 * 8];      // W1^T tf32, K padded 5->8
__device__ __align__(16) float g_Wt2[64 * 32];
__device__ __align__(16) float g_Wt3[128 * 64];
__device__ __align__(16) float g_Wt4[256 * 128];
__device__ float g_pool[NG * 256];
__device__ float g_gcnt[NG];

// ---------------- init: zero + all weight transposes/rounds -----------------
__global__ void init_kernel(const float* __restrict__ W1, const float* __restrict__ W2,
                            const float* __restrict__ W3, const float* __restrict__ W4) {
    int i = blockIdx.x * blockDim.x + threadIdx.x;
    if (i < NN) g_cnt[i] = 0;
    if (i < NG * 256) g_pool[i] = 0.f;
    if (i < NG) g_gcnt[i] = 0.f;
    if (i < 32 * 8) {
        int n = i >> 3, k = i & 7;
        g_Wt1[i] = (k < 5) ? __uint_as_float(f2tf32(W1[k * 32 + n])) : 0.f;
    }
    if (i < 64 * 32) {
        int n = i >> 5, k = i & 31;
        g_Wt2[i] = __uint_as_float(f2tf32(W2[k * 64 + n]));
    }
    if (i < 128 * 64) {
        int n = i >> 6, k = i & 63;
        g_Wt3[i] = __uint_as_float(f2tf32(W3[k * 128 + n]));
    }
    if (i < 256 * 128) {
        int n = i >> 7, k = i & 127;
        g_Wt4[i] = __uint_as_float(f2tf32(W4[k * 256 + n]));
    }
}

__global__ void count_kernel(const int* __restrict__ ei) {
    int e = blockIdx.x * blockDim.x + threadIdx.x;
    if (e < NE) atomicAdd(&g_cnt[ei[NE + e]], 1);
}

__global__ void chunkred_kernel() {
    int c = blockIdx.x, tid = threadIdx.x;
    int base = c * CHUNK;
    int s = 0;
    #pragma unroll
    for (int k = 0; k < CHUNK / 256; k++) {
        int idx = base + tid + k * 256;
        if (idx < NN) {
            int v = g_cnt[idx];
            s += v;
            g_dinv[idx] = rsqrtf((float)(v + 1));
        }
    }
    for (int off = 16; off; off >>= 1) s += __shfl_down_sync(~0u, s, off);
    __shared__ int sm[8];
    if ((tid & 31) == 0) sm[tid >> 5] = s;
    __syncthreads();
    if (tid < 8) {
        int t = sm[tid];
        for (int off = 4; off; off >>= 1) t += __shfl_down_sync(0xff, t, off);
        if (tid == 0) g_chunksum[c] = t;
    }
}

// per-chunk scan (self-deriving base) + fused x -> zx = bf16(dinv*x) convert
__global__ void scan2_kernel(const float* __restrict__ x) {
    __shared__ int warpsum[32];
    __shared__ int part[2];
    __shared__ int base_s;
    int c = blockIdx.x, tid = threadIdx.x;

    if (tid < 64) {
        int v = (tid < c && tid < NCHUNK) ? g_chunksum[tid] : 0;
        for (int off = 16; off; off >>= 1) v += __shfl_down_sync(~0u, v, off);
        if ((tid & 31) == 0) part[tid >> 5] = v;
    }
    __syncthreads();
    if (tid == 0) base_s = part[0] + part[1];
    __syncthreads();

    int i = c * CHUNK + tid;
    int v = (i < NN) ? g_cnt[i] : 0;
    int lane = tid & 31, w = tid >> 5;
    int incl = v;
    for (int off = 1; off < 32; off <<= 1) {
        int t = __shfl_up_sync(~0u, incl, off);
        if (lane >= off) incl += t;
    }
    if (lane == 31) warpsum[w] = incl;
    __syncthreads();
    if (w == 0) {
        int ws = warpsum[lane];
        for (int off = 1; off < 32; off <<= 1) {
            int t = __shfl_up_sync(~0u, ws, off);
            if (lane >= off) ws += t;
        }
        warpsum[lane] = ws;
    }
    __syncthreads();
    int excl = incl - v + (w > 0 ? warpsum[w - 1] : 0) + base_s;
    if (i < NN) {
        g_rowptr[i] = excl; g_cursor[i] = excl;
        float dv = g_dinv[i];
        float v0 = x[(size_t)i * 5 + 0], v1 = x[(size_t)i * 5 + 1];
        float v2 = x[(size_t)i * 5 + 2], v3 = x[(size_t)i * 5 + 3];
        float v4 = x[(size_t)i * 5 + 4];
        uint4 pk;
        pk.x = pack_bf2(dv * v0, dv * v1);
        pk.y = pack_bf2(dv * v2, dv * v3);
        pk.z = pack_bf2(dv * v4, 0.f);
        pk.w = 0u;
        *(uint4*)(g_zx + (size_t)i * 8) = pk;
    }
    if (i == NN - 1) g_rowptr[NN] = excl + v;
}

__global__ void fillg_kernel(const int* __restrict__ ei, const int* __restrict__ bat) {
    int e = blockIdx.x * blockDim.x + threadIdx.x;
    if (e < NE) {
        int s = ei[e];
        int d = ei[NE + e];
        int pos = atomicAdd(&g_cursor[d], 1);
        g_col[pos] = s;
    }
    if (e < NN) atomicAdd(&g_gcnt[bat[e]], 1.f);
}

// ---------------- aggregation (unweighted z-gather, final dinv scale) -------
// layer 1: F=8 (one uint4 per node), one thread per node
__global__ void agg1_kernel(const uint4* __restrict__ z, uint4* __restrict__ out) {
    int node = blockIdx.x * blockDim.x + threadIdx.x;
    if (node >= NN) return;
    float acc[8];
    {
        uint4 v = __ldg(&z[node]);
        const uint32_t* u = (const uint32_t*)&v;
        #pragma unroll
        for (int j = 0; j < 4; j++) {
            float2 fv = unpack_bf2(u[j]);
            acc[2 * j] = fv.x; acc[2 * j + 1] = fv.y;
        }
    }
    int e = g_rowptr[node], end = g_rowptr[node + 1];
    for (; e + 3 < end; e += 4) {
        int c0 = __ldg(&g_col[e]),     c1 = __ldg(&g_col[e + 1]);
        int c2 = __ldg(&g_col[e + 2]), c3 = __ldg(&g_col[e + 3]);
        uint4 v0 = __ldg(&z[c0]), v1 = __ldg(&z[c1]);
        uint4 v2 = __ldg(&z[c2]), v3 = __ldg(&z[c3]);
        const uint32_t* u0 = (const uint32_t*)&v0;
        const uint32_t* u1 = (const uint32_t*)&v1;
        const uint32_t* u2 = (const uint32_t*)&v2;
        const uint32_t* u3 = (const uint32_t*)&v3;
        #pragma unroll
        for (int j = 0; j < 4; j++) {
            float2 f0 = unpack_bf2(u0[j]), f1 = unpack_bf2(u1[j]);
            float2 f2 = unpack_bf2(u2[j]), f3 = unpack_bf2(u3[j]);
            acc[2 * j]     += f0.x + f1.x + f2.x + f3.x;
            acc[2 * j + 1] += f0.y + f1.y + f2.y + f3.y;
        }
    }
    for (; e < end; e++) {
        uint4 v0 = __ldg(&z[__ldg(&g_col[e])]);
        const uint32_t* u0 = (const uint32_t*)&v0;
        #pragma unroll
        for (int j = 0; j < 4; j++) {
            float2 f0 = unpack_bf2(u0[j]);
            acc[2 * j] += f0.x; acc[2 * j + 1] += f0.y;
        }
    }
    float dv = g_dinv[node];
    uint32_t pk[4];
    #pragma unroll
    for (int j = 0; j < 4; j++) pk[j] = pack_bf2(dv * acc[2 * j], dv * acc[2 * j + 1]);
    out[node] = *(uint4*)pk;
}

// layers 2-4: F in {32,64,128}, threads.x = F/8 (one uint4 per thread)
template <int F>
__global__ void aggb_kernel(const uint4* __restrict__ z, uint4* __restrict__ out) {
    constexpr int FQ8 = F / 8;
    int node = blockIdx.x * blockDim.y + threadIdx.y;
    if (node >= NN) return;
    int f = threadIdx.x;
    float acc[8];
    {
        uint4 v = __ldg(&z[(size_t)node * FQ8 + f]);
        const uint32_t* u = (const uint32_t*)&v;
        #pragma unroll
        for (int j = 0; j < 4; j++) {
            float2 fv = unpack_bf2(u[j]);
            acc[2 * j] = fv.x; acc[2 * j + 1] = fv.y;
        }
    }
    int e = g_rowptr[node], end = g_rowptr[node + 1];
    for (; e + 3 < end; e += 4) {
        int c0 = __ldg(&g_col[e]),     c1 = __ldg(&g_col[e + 1]);
        int c2 = __ldg(&g_col[e + 2]), c3 = __ldg(&g_col[e + 3]);
        uint4 v0 = __ldg(&z[(size_t)c0 * FQ8 + f]);
        uint4 v1 = __ldg(&z[(size_t)c1 * FQ8 + f]);
        uint4 v2 = __ldg(&z[(size_t)c2 * FQ8 + f]);
        uint4 v3 = __ldg(&z[(size_t)c3 * FQ8 + f]);
        const uint32_t* u0 = (const uint32_t*)&v0;
        const uint32_t* u1 = (const uint32_t*)&v1;
        const uint32_t* u2 = (const uint32_t*)&v2;
        const uint32_t* u3 = (const uint32_t*)&v3;
        #pragma unroll
        for (int j = 0; j < 4; j++) {
            float2 f0 = unpack_bf2(u0[j]), f1 = unpack_bf2(u1[j]);
            float2 f2 = unpack_bf2(u2[j]), f3 = unpack_bf2(u3[j]);
            acc[2 * j]     += f0.x + f1.x + f2.x + f3.x;
            acc[2 * j + 1] += f0.y + f1.y + f2.y + f3.y;
        }
    }
    for (; e < end; e++) {
        uint4 v0 = __ldg(&z[(size_t)__ldg(&g_col[e]) * FQ8 + f]);
        const uint32_t* u0 = (const uint32_t*)&v0;
        #pragma unroll
        for (int j = 0; j < 4; j++) {
            float2 f0 = unpack_bf2(u0[j]);
            acc[2 * j] += f0.x; acc[2 * j + 1] += f0.y;
        }
    }
    float dv = g_dinv[node];
    uint32_t pk[4];
    #pragma unroll
    for (int j = 0; j < 4; j++) pk[j] = pack_bf2(dv * acc[2 * j], dv * acc[2 * j + 1]);
    out[(size_t)node * FQ8 + f] = *(uint4*)pk;
}

// ---------------- tf32 mma: out = post(A @ W^T + b) -------------------------
// A: [NN][K] bf16, Wt: [NTOT][K] tf32-in-f32.
// SCALE=1: out = bf16(dinv_row * relu(...)) (z-form); SCALE=0: out = bf16(relu(...)).
template <int K, int NTOT, int SCALE>
__global__ __launch_bounds__(256) void mma_kernel(
    const __nv_bfloat16* __restrict__ A, const float* __restrict__ Wt,
    const float* __restrict__ bias, __nv_bfloat16* __restrict__ out)
{
    constexpr int NS = (NTOT < 128) ? NTOT : 128;
    constexpr int AS = K + 4;
    constexpr int KQ = K / 4;
    constexpr int KQ8 = K / 8;
    extern __shared__ float smem[];
    float* sA = smem;             // [128][AS]
    float* sB = smem + 128 * AS;  // [NS][AS]
    int tid = threadIdx.x;
    int node0 = blockIdx.x * 128;
    int n0 = blockIdx.y * NS;

    const uint4* Ab = (const uint4*)A;
    for (int i = tid; i < 128 * KQ8; i += 256) {
        int r = i / KQ8, c = i - r * KQ8;
        int nd = node0 + r;
        uint4 v = make_uint4(0, 0, 0, 0);
        if (nd < NN) v = __ldg(&Ab[(size_t)nd * KQ8 + c]);
        const uint32_t* u = (const uint32_t*)&v;
        float* dst = sA + r * AS + c * 8;
        #pragma unroll
        for (int j = 0; j < 4; j++) {
            float2 fv = unpack_bf2(u[j]);
            dst[2 * j] = fv.x; dst[2 * j + 1] = fv.y;
        }
    }
    for (int i = tid; i < NS * KQ; i += 256) {
        int r = i / KQ, kq = i - r * KQ;
        float4 v = __ldg((const float4*)Wt + (size_t)(n0 + r) * KQ + kq);
        *(float4*)(sB + r * AS + kq * 4) = v;
    }
    __syncthreads();

    int warp = tid >> 5, lane = tid & 31;
    int g = lane >> 2, tg = lane & 3;
    int mrow = warp * 16;

    uint32_t a[KQ8][4];
    #pragma unroll
    for (int kk = 0; kk < KQ8; kk++) {
        const float* p0 = sA + (mrow + g) * AS + kk * 8 + tg;
        const float* p1 = sA + (mrow + g + 8) * AS + kk * 8 + tg;
        a[kk][0] = __float_as_uint(p0[0]);
        a[kk][1] = __float_as_uint(p1[0]);
        a[kk][2] = __float_as_uint(p0[4]);
        a[kk][3] = __float_as_uint(p1[4]);
    }

    int row0 = node0 + mrow + g;
    int row1 = row0 + 8;
    float sc0 = 1.f, sc1 = 1.f;
    if (SCALE) {
        if (row0 < NN) sc0 = __ldg(&g_dinv[row0]);
        if (row1 < NN) sc1 = __ldg(&g_dinv[row1]);
    }
    #pragma unroll 2
    for (int ng = 0; ng < NS / 8; ng++) {
        float d0 = 0.f, d1 = 0.f, d2 = 0.f, d3 = 0.f;
        const float* bp = sB + (ng * 8 + g) * AS + tg;
        #pragma unroll
        for (int kk = 0; kk < KQ8; kk++) {
            uint32_t b0 = __float_as_uint(bp[kk * 8]);
            uint32_t b1 = __float_as_uint(bp[kk * 8 + 4]);
            asm volatile(
                "mma.sync.aligned.m16n8k8.row.col.f32.tf32.tf32.f32 "
                "{%0,%1,%2,%3}, {%4,%5,%6,%7}, {%8,%9}, {%0,%1,%2,%3};"
                : "+f"(d0), "+f"(d1), "+f"(d2), "+f"(d3)
                : "r"(a[kk][0]), "r"(a[kk][1]), "r"(a[kk][2]), "r"(a[kk][3]),
                  "r"(b0), "r"(b1));
        }
        int col = n0 + ng * 8 + 2 * tg;
        float2 bs = __ldg((const float2*)&bias[col]);
        if (row0 < NN)
            *(uint32_t*)(out + (size_t)row0 * NTOT + col) =
                pack_bf2(fmaxf(d0 + bs.x, 0.f) * sc0, fmaxf(d1 + bs.y, 0.f) * sc0);
        if (row1 < NN)
            *(uint32_t*)(out + (size_t)row1 * NTOT + col) =
                pack_bf2(fmaxf(d2 + bs.x, 0.f) * sc1, fmaxf(d3 + bs.y, 0.f) * sc1);
    }
}

// ---------------- mean-pool (bf16 in) + head --------------------------------
__global__ void poolb_kernel(const __nv_bfloat16* __restrict__ h,
                             const int* __restrict__ batch) {
    const int CH = 64;
    int f = threadIdx.x;
    int n0 = blockIdx.x * CH;
    float acc = 0.f;
    int curg = -1;
    for (int i = 0; i < CH; i++) {
        int nd = n0 + i;
        if (nd >= NN) break;
        int g = batch[nd];
        if (g != curg) {
            if (curg >= 0) atomicAdd(&g_pool[curg * 256 + f], acc);
            acc = 0.f; curg = g;
        }
        acc += __bfloat162float(h[(size_t)nd * 256 + f]);
    }
    if (curg >= 0) atomicAdd(&g_pool[curg * 256 + f], acc);
}

__global__ void head_kernel(const float* __restrict__ fcW, const float* __restrict__ fcb,
                            float* __restrict__ out) {
    __shared__ float slog[NG * NC];
    int tid = threadIdx.x;
    if (tid < NG * NC) {
        int g = tid / NC, c = tid % NC;
        float inv = 1.f / fmaxf(g_gcnt[g], 1.f);
        float a = fcb[c];
        for (int k = 0; k < 256; k++)
            a += g_pool[g * 256 + k] * inv * fcW[k * NC + c];
        slog[tid] = a;
    }
    __syncthreads();
    if (tid < NG * NC) {
        int g = tid / NC;
        float m = -1e30f;
        for (int i = 0; i < NC; i++) m = fmaxf(m, slog[g * NC + i]);
        float s = 0.f;
        for (int i = 0; i < NC; i++) s += expf(slog[g * NC + i] - m);
        out[tid] = slog[tid] - m - logf(s);
    }
}

// ---------------- launch -----------------------------------------------------
extern "C" void kernel_launch(void* const* d_in, const int* in_sizes, int n_in,
                              void* d_out, int out_size) {
    const float* x   = (const float*)d_in[0];
    const int*   ei  = (const int*)d_in[1];
    const int*   bat = (const int*)d_in[2];
    const float* W1 = (const float*)d_in[3];
    const float* b1 = (const float*)d_in[4];
    const float* W2 = (const float*)d_in[5];
    const float* b2 = (const float*)d_in[6];
    const float* W3 = (const float*)d_in[7];
    const float* b3 = (const float*)d_in[8];
    const float* W4 = (const float*)d_in[9];
    const float* b4 = (const float*)d_in[10];
    const float* fcW = (const float*)d_in[11];
    const float* fcb = (const float*)d_in[12];
    float* out = (float*)d_out;

    float *Wt1, *Wt2, *Wt3, *Wt4;
    __nv_bfloat16 *zx, *bA, *bB, *hO;
    cudaGetSymbolAddress((void**)&zx, g_zx);
    cudaGetSymbolAddress((void**)&bA, g_b16A);
    cudaGetSymbolAddress((void**)&bB, g_b16B);
    cudaGetSymbolAddress((void**)&hO, g_hO);
    cudaGetSymbolAddress((void**)&Wt1, g_Wt1);
    cudaGetSymbolAddress((void**)&Wt2, g_Wt2);
    cudaGetSymbolAddress((void**)&Wt3, g_Wt3);
    cudaGetSymbolAddress((void**)&Wt4, g_Wt4);

    const int smL1 = (128 * (8 + 4) + 32 * (8 + 4)) * 4;        // 7680
    const int smL2 = (128 * (32 + 4) + 64 * (32 + 4)) * 4;      // 27648
    const int smL3 = (128 * (64 + 4) + 128 * (64 + 4)) * 4;     // 69632
    const int smL4 = (128 * (128 + 4) + 128 * (128 + 4)) * 4;   // 135168
    cudaFuncSetAttribute(mma_kernel<64, 128, 1>,
                         cudaFuncAttributeMaxDynamicSharedMemorySize, smL3);
    cudaFuncSetAttribute(mma_kernel<128, 256, 0>,
                         cudaFuncAttributeMaxDynamicSharedMemorySize, smL4);

    const int EB = (NE + 255) / 256;
    const int NB = (NN + 255) / 256;

    init_kernel<<<NB, 256>>>(W1, W2, W3, W4);
    count_kernel<<<EB, 256>>>(ei);
    chunkred_kernel<<<NCHUNK, 256>>>();
    scan2_kernel<<<NCHUNK, 1024>>>(x);
    fillg_kernel<<<EB, 256>>>(ei, bat);

    // layer 1: agg1(zx)[8] -> bB; mma K=8 -> bA z1 [NN][32]
    agg1_kernel<<<NB, 256>>>((const uint4*)zx, (uint4*)bB);
    mma_kernel<8, 32, 1><<<dim3(391, 1), 256, smL1>>>(bB, Wt1, b1, bA);
    // layer 2: aggb(bA)[32] -> bB; mma K=32 -> bA z2 [NN][64]
    {
        dim3 blk(4, 64);
        aggb_kernel<32><<<(NN + 63) / 64, blk>>>((const uint4*)bA, (uint4*)bB);
        mma_kernel<32, 64, 1><<<dim3(391, 1), 256, smL2>>>(bB, Wt2, b2, bA);
    }
    // layer 3: aggb(bA)[64] -> bB; mma K=64 -> bA z3 [NN][128]
    {
        dim3 blk(8, 32);
        aggb_kernel<64><<<(NN + 31) / 32, blk>>>((const uint4*)bA, (uint4*)bB);
        mma_kernel<64, 128, 1><<<dim3(391, 1), 256, smL3>>>(bB, Wt3, b3, bA);
    }
    // layer 4: aggb(bA)[128] -> bB; mma K=128 -> hO h4 [NN][256]
    {
        dim3 blk(16, 16);
        aggb_kernel<128><<<(NN + 15) / 16, blk>>>((const uint4*)bA, (uint4*)bB);
        mma_kernel<128, 256, 0><<<dim3(391, 2), 256, smL4>>>(bB, Wt4, b4, hO);
    }

    // mean pool + head
    poolb_kernel<<<(NN + 63) / 64, 256>>>(hO, bat);
    head_kernel<<<1, 640>>>(fcW, fcb, out);

    (void)in_sizes; (void)n_in; (void)out_size;
}

// round 12
// speedup vs baseline: 1.2843x; 1.0542x over previous
#include <cuda_runtime.h>
#include <cuda_bf16.h>
#include <math.h>
#include <stdint.h>

#define NN 50000
#define NE 800000
#define NG 64
#define NC 10
#define CHUNK 1024
#define NCHUNK ((NN + CHUNK - 1) / CHUNK)   // 49

__device__ __forceinline__ uint32_t f2tf32(float x) {
    uint32_t u;
    asm("cvt.rna.tf32.f32 %0, %1;" : "=r"(u) : "f"(x));
    return u;
}
__device__ __forceinline__ uint32_t pack_bf2(float a, float b) {
    __nv_bfloat162 p = __floats2bfloat162_rn(a, b);
    return *(uint32_t*)&p;
}
__device__ __forceinline__ float2 unpack_bf2(uint32_t u) {
    return __bfloat1622float2(*(__nv_bfloat162*)&u);
}

// ---------------- scratch ----------------------------------------------------
__device__ __align__(16) float g_dinv[NN];
__device__ int   g_cnt[NN];
__device__ int   g_rowptr[NN + 1];
__device__ int   g_cursor[NN];
__device__ __align__(16) unsigned short g_col[NE];   // node ids < 65536
__device__ int   g_chunksum[NCHUNK];
__device__ __align__(16) __nv_bfloat16 g_zx[NN * 8];     // dinv*x, bf16, padded
__device__ __align__(16) __nv_bfloat16 g_b16A[NN * 128];
__device__ __align__(16) __nv_bfloat16 g_b16B[NN * 128];
__device__ __align__(16) __nv_bfloat16 g_hO[NN * 256];
__device__ __align__(16) float g_Wt1[32 * 8];      // W1^T tf32, K padded 5->8
__device__ __align__(16) float g_Wt2[64 * 32];
__device__ __align__(16) float g_Wt3[128 * 64];
__device__ __align__(16) float g_Wt4[256 * 128];
__device__ float g_pool[NG * 256];
__device__ float g_gcnt[NG];

// ---------------- init: zero + all weight transposes/rounds -----------------
__global__ void init_kernel(const float* __restrict__ W1, const float* __restrict__ W2,
                            const float* __restrict__ W3, const float* __restrict__ W4) {
    int i = blockIdx.x * blockDim.x + threadIdx.x;
    if (i < NN) g_cnt[i] = 0;
    if (i < NG * 256) g_pool[i] = 0.f;
    if (i < NG) g_gcnt[i] = 0.f;
    if (i < 32 * 8) {
        int n = i >> 3, k = i & 7;
        g_Wt1[i] = (k < 5) ? __uint_as_float(f2tf32(W1[k * 32 + n])) : 0.f;
    }
    if (i < 64 * 32) {
        int n = i >> 5, k = i & 31;
        g_Wt2[i] = __uint_as_float(f2tf32(W2[k * 64 + n]));
    }
    if (i < 128 * 64) {
        int n = i >> 6, k = i & 63;
        g_Wt3[i] = __uint_as_float(f2tf32(W3[k * 128 + n]));
    }
    if (i < 256 * 128) {
        int n = i >> 7, k = i & 127;
        g_Wt4[i] = __uint_as_float(f2tf32(W4[k * 256 + n]));
    }
}

__global__ void count_kernel(const int* __restrict__ ei) {
    int e = blockIdx.x * blockDim.x + threadIdx.x;
    if (e < NE) atomicAdd(&g_cnt[ei[NE + e]], 1);
}

__global__ void chunkred_kernel() {
    int c = blockIdx.x, tid = threadIdx.x;
    int base = c * CHUNK;
    int s = 0;
    #pragma unroll
    for (int k = 0; k < CHUNK / 256; k++) {
        int idx = base + tid + k * 256;
        if (idx < NN) {
            int v = g_cnt[idx];
            s += v;
            g_dinv[idx] = rsqrtf((float)(v + 1));
        }
    }
    for (int off = 16; off; off >>= 1) s += __shfl_down_sync(~0u, s, off);
    __shared__ int sm[8];
    if ((tid & 31) == 0) sm[tid >> 5] = s;
    __syncthreads();
    if (tid < 8) {
        int t = sm[tid];
        for (int off = 4; off; off >>= 1) t += __shfl_down_sync(0xff, t, off);
        if (tid == 0) g_chunksum[c] = t;
    }
}

// per-chunk scan (self-deriving base) + fused x -> zx = bf16(dinv*x) convert
__global__ void scan2_kernel(const float* __restrict__ x) {
    __shared__ int warpsum[32];
    __shared__ int part[2];
    __shared__ int base_s;
    int c = blockIdx.x, tid = threadIdx.x;

    if (tid < 64) {
        int v = (tid < c && tid < NCHUNK) ? g_chunksum[tid] : 0;
        for (int off = 16; off; off >>= 1) v += __shfl_down_sync(~0u, v, off);
        if ((tid & 31) == 0) part[tid >> 5] = v;
    }
    __syncthreads();
    if (tid == 0) base_s = part[0] + part[1];
    __syncthreads();

    int i = c * CHUNK + tid;
    int v = (i < NN) ? g_cnt[i] : 0;
    int lane = tid & 31, w = tid >> 5;
    int incl = v;
    for (int off = 1; off < 32; off <<= 1) {
        int t = __shfl_up_sync(~0u, incl, off);
        if (lane >= off) incl += t;
    }
    if (lane == 31) warpsum[w] = incl;
    __syncthreads();
    if (w == 0) {
        int ws = warpsum[lane];
        for (int off = 1; off < 32; off <<= 1) {
            int t = __shfl_up_sync(~0u, ws, off);
            if (lane >= off) ws += t;
        }
        warpsum[lane] = ws;
    }
    __syncthreads();
    int excl = incl - v + (w > 0 ? warpsum[w - 1] : 0) + base_s;
    if (i < NN) {
        g_rowptr[i] = excl; g_cursor[i] = excl;
        float dv = g_dinv[i];
        float v0 = x[(size_t)i * 5 + 0], v1 = x[(size_t)i * 5 + 1];
        float v2 = x[(size_t)i * 5 + 2], v3 = x[(size_t)i * 5 + 3];
        float v4 = x[(size_t)i * 5 + 4];
        uint4 pk;
        pk.x = pack_bf2(dv * v0, dv * v1);
        pk.y = pack_bf2(dv * v2, dv * v3);
        pk.z = pack_bf2(dv * v4, 0.f);
        pk.w = 0u;
        *(uint4*)(g_zx + (size_t)i * 8) = pk;
    }
    if (i == NN - 1) g_rowptr[NN] = excl + v;
}

__global__ void fillg_kernel(const int* __restrict__ ei, const int* __restrict__ bat) {
    int e = blockIdx.x * blockDim.x + threadIdx.x;
    if (e < NE) {
        int s = ei[e];
        int d = ei[NE + e];
        int pos = atomicAdd(&g_cursor[d], 1);
        g_col[pos] = (unsigned short)s;
    }
    if (e < NN) atomicAdd(&g_gcnt[bat[e]], 1.f);
}

// ---------------- aggregation (unweighted z-gather, final dinv scale) -------
// layer 1: F=8 (one uint4 per node), one thread per node
__global__ void agg1_kernel(const uint4* __restrict__ z, uint4* __restrict__ out) {
    int node = blockIdx.x * blockDim.x + threadIdx.x;
    if (node >= NN) return;
    float acc[8];
    {
        uint4 v = __ldg(&z[node]);
        const uint32_t* u = (const uint32_t*)&v;
        #pragma unroll
        for (int j = 0; j < 4; j++) {
            float2 fv = unpack_bf2(u[j]);
            acc[2 * j] = fv.x; acc[2 * j + 1] = fv.y;
        }
    }
    int e = g_rowptr[node], end = g_rowptr[node + 1];
    for (; e + 3 < end; e += 4) {
        int c0 = __ldg(&g_col[e]),     c1 = __ldg(&g_col[e + 1]);
        int c2 = __ldg(&g_col[e + 2]), c3 = __ldg(&g_col[e + 3]);
        uint4 v0 = __ldg(&z[c0]), v1 = __ldg(&z[c1]);
        uint4 v2 = __ldg(&z[c2]), v3 = __ldg(&z[c3]);
        const uint32_t* u0 = (const uint32_t*)&v0;
        const uint32_t* u1 = (const uint32_t*)&v1;
        const uint32_t* u2 = (const uint32_t*)&v2;
        const uint32_t* u3 = (const uint32_t*)&v3;
        #pragma unroll
        for (int j = 0; j < 4; j++) {
            float2 f0 = unpack_bf2(u0[j]), f1 = unpack_bf2(u1[j]);
            float2 f2 = unpack_bf2(u2[j]), f3 = unpack_bf2(u3[j]);
            acc[2 * j]     += f0.x + f1.x + f2.x + f3.x;
            acc[2 * j + 1] += f0.y + f1.y + f2.y + f3.y;
        }
    }
    for (; e < end; e++) {
        uint4 v0 = __ldg(&z[__ldg(&g_col[e])]);
        const uint32_t* u0 = (const uint32_t*)&v0;
        #pragma unroll
        for (int j = 0; j < 4; j++) {
            float2 f0 = unpack_bf2(u0[j]);
            acc[2 * j] += f0.x; acc[2 * j + 1] += f0.y;
        }
    }
    float dv = g_dinv[node];
    uint32_t pk[4];
    #pragma unroll
    for (int j = 0; j < 4; j++) pk[j] = pack_bf2(dv * acc[2 * j], dv * acc[2 * j + 1]);
    out[node] = *(uint4*)pk;
}

// layers 2-4: F in {32,64,128}, threads.x = F/8 (one uint4 per thread)
template <int F>
__global__ void aggb_kernel(const uint4* __restrict__ z, uint4* __restrict__ out) {
    constexpr int FQ8 = F / 8;
    int node = blockIdx.x * blockDim.y + threadIdx.y;
    if (node >= NN) return;
    int f = threadIdx.x;
    float acc[8];
    {
        uint4 v = __ldg(&z[(size_t)node * FQ8 + f]);
        const uint32_t* u = (const uint32_t*)&v;
        #pragma unroll
        for (int j = 0; j < 4; j++) {
            float2 fv = unpack_bf2(u[j]);
            acc[2 * j] = fv.x; acc[2 * j + 1] = fv.y;
        }
    }
    int e = g_rowptr[node], end = g_rowptr[node + 1];
    for (; e + 3 < end; e += 4) {
        int c0 = __ldg(&g_col[e]),     c1 = __ldg(&g_col[e + 1]);
        int c2 = __ldg(&g_col[e + 2]), c3 = __ldg(&g_col[e + 3]);
        uint4 v0 = __ldg(&z[(size_t)c0 * FQ8 + f]);
        uint4 v1 = __ldg(&z[(size_t)c1 * FQ8 + f]);
        uint4 v2 = __ldg(&z[(size_t)c2 * FQ8 + f]);
        uint4 v3 = __ldg(&z[(size_t)c3 * FQ8 + f]);
        const uint32_t* u0 = (const uint32_t*)&v0;
        const uint32_t* u1 = (const uint32_t*)&v1;
        const uint32_t* u2 = (const uint32_t*)&v2;
        const uint32_t* u3 = (const uint32_t*)&v3;
        #pragma unroll
        for (int j = 0; j < 4; j++) {
            float2 f0 = unpack_bf2(u0[j]), f1 = unpack_bf2(u1[j]);
            float2 f2 = unpack_bf2(u2[j]), f3 = unpack_bf2(u3[j]);
            acc[2 * j]     += f0.x + f1.x + f2.x + f3.x;
            acc[2 * j + 1] += f0.y + f1.y + f2.y + f3.y;
        }
    }
    for (; e < end; e++) {
        uint4 v0 = __ldg(&z[(size_t)__ldg(&g_col[e]) * FQ8 + f]);
        const uint32_t* u0 = (const uint32_t*)&v0;
        #pragma unroll
        for (int j = 0; j < 4; j++) {
            float2 f0 = unpack_bf2(u0[j]);
            acc[2 * j] += f0.x; acc[2 * j + 1] += f0.y;
        }
    }
    float dv = g_dinv[node];
    uint32_t pk[4];
    #pragma unroll
    for (int j = 0; j < 4; j++) pk[j] = pack_bf2(dv * acc[2 * j], dv * acc[2 * j + 1]);
    out[(size_t)node * FQ8 + f] = *(uint4*)pk;
}

// ---------------- tf32 mma (tiled, layers 1-3): out = post(A @ W^T + b) -----
template <int K, int NTOT, int SCALE>
__global__ __launch_bounds__(256) void mma_kernel(
    const __nv_bfloat16* __restrict__ A, const float* __restrict__ Wt,
    const float* __restrict__ bias, __nv_bfloat16* __restrict__ out)
{
    constexpr int NS = (NTOT < 128) ? NTOT : 128;
    constexpr int AS = K + 4;
    constexpr int KQ = K / 4;
    constexpr int KQ8 = K / 8;
    extern __shared__ float smem[];
    float* sA = smem;             // [128][AS]
    float* sB = smem + 128 * AS;  // [NS][AS]
    int tid = threadIdx.x;
    int node0 = blockIdx.x * 128;
    int n0 = blockIdx.y * NS;

    const uint4* Ab = (const uint4*)A;
    for (int i = tid; i < 128 * KQ8; i += 256) {
        int r = i / KQ8, c = i - r * KQ8;
        int nd = node0 + r;
        uint4 v = make_uint4(0, 0, 0, 0);
        if (nd < NN) v = __ldg(&Ab[(size_t)nd * KQ8 + c]);
        const uint32_t* u = (const uint32_t*)&v;
        float* dst = sA + r * AS + c * 8;
        #pragma unroll
        for (int j = 0; j < 4; j++) {
            float2 fv = unpack_bf2(u[j]);
            dst[2 * j] = fv.x; dst[2 * j + 1] = fv.y;
        }
    }
    for (int i = tid; i < NS * KQ; i += 256) {
        int r = i / KQ, kq = i - r * KQ;
        float4 v = __ldg((const float4*)Wt + (size_t)(n0 + r) * KQ + kq);
        *(float4*)(sB + r * AS + kq * 4) = v;
    }
    __syncthreads();

    int warp = tid >> 5, lane = tid & 31;
    int g = lane >> 2, tg = lane & 3;
    int mrow = warp * 16;

    uint32_t a[KQ8][4];
    #pragma unroll
    for (int kk = 0; kk < KQ8; kk++) {
        const float* p0 = sA + (mrow + g) * AS + kk * 8 + tg;
        const float* p1 = sA + (mrow + g + 8) * AS + kk * 8 + tg;
        a[kk][0] = __float_as_uint(p0[0]);
        a[kk][1] = __float_as_uint(p1[0]);
        a[kk][2] = __float_as_uint(p0[4]);
        a[kk][3] = __float_as_uint(p1[4]);
    }

    int row0 = node0 + mrow + g;
    int row1 = row0 + 8;
    float sc0 = 1.f, sc1 = 1.f;
    if (SCALE) {
        if (row0 < NN) sc0 = __ldg(&g_dinv[row0]);
        if (row1 < NN) sc1 = __ldg(&g_dinv[row1]);
    }
    #pragma unroll 2
    for (int ng = 0; ng < NS / 8; ng++) {
        float d0 = 0.f, d1 = 0.f, d2 = 0.f, d3 = 0.f;
        const float* bp = sB + (ng * 8 + g) * AS + tg;
        #pragma unroll
        for (int kk = 0; kk < KQ8; kk++) {
            uint32_t b0 = __float_as_uint(bp[kk * 8]);
            uint32_t b1 = __float_as_uint(bp[kk * 8 + 4]);
            asm volatile(
                "mma.sync.aligned.m16n8k8.row.col.f32.tf32.tf32.f32 "
                "{%0,%1,%2,%3}, {%4,%5,%6,%7}, {%8,%9}, {%0,%1,%2,%3};"
                : "+f"(d0), "+f"(d1), "+f"(d2), "+f"(d3)
                : "r"(a[kk][0]), "r"(a[kk][1]), "r"(a[kk][2]), "r"(a[kk][3]),
                  "r"(b0), "r"(b1));
        }
        int col = n0 + ng * 8 + 2 * tg;
        float2 bs = __ldg((const float2*)&bias[col]);
        if (row0 < NN)
            *(uint32_t*)(out + (size_t)row0 * NTOT + col) =
                pack_bf2(fmaxf(d0 + bs.x, 0.f) * sc0, fmaxf(d1 + bs.y, 0.f) * sc0);
        if (row1 < NN)
            *(uint32_t*)(out + (size_t)row1 * NTOT + col) =
                pack_bf2(fmaxf(d2 + bs.x, 0.f) * sc1, fmaxf(d3 + bs.y, 0.f) * sc1);
    }
}

// ---------------- persistent tf32 mma for layer 4 (K=128, N=256) ------------
// B (full W4) staged once per CTA; loop over M-tiles staging only A.
__global__ __launch_bounds__(256) void mma_l4_kernel(
    const __nv_bfloat16* __restrict__ A, const float* __restrict__ Wt,
    const float* __restrict__ bias, __nv_bfloat16* __restrict__ out)
{
    constexpr int K = 128, NTOT = 256, NS = 256;
    constexpr int AS = K + 4;
    constexpr int KQ = K / 4;
    constexpr int KQ8 = K / 8;
    constexpr int NTILES = (NN + 127) / 128;   // 391
    extern __shared__ float smem[];
    float* sA = smem;             // [128][AS] = 67.6 KB
    float* sB = smem + 128 * AS;  // [256][AS] = 135.2 KB
    int tid = threadIdx.x;

    // stage all of W4 once
    for (int i = tid; i < NS * KQ; i += 256) {
        int r = i / KQ, kq = i - r * KQ;
        float4 v = __ldg((const float4*)Wt + (size_t)r * KQ + kq);
        *(float4*)(sB + r * AS + kq * 4) = v;
    }

    int warp = tid >> 5, lane = tid & 31;
    int g = lane >> 2, tg = lane & 3;
    int mrow = warp * 16;
    const uint4* Ab = (const uint4*)A;

    for (int tile = blockIdx.x; tile < NTILES; tile += gridDim.x) {
        int node0 = tile * 128;
        __syncthreads();   // sA reuse (and first-iter sB visibility)
        for (int i = tid; i < 128 * KQ8; i += 256) {
            int r = i / KQ8, c = i - r * KQ8;
            int nd = node0 + r;
            uint4 v = make_uint4(0, 0, 0, 0);
            if (nd < NN) v = __ldg(&Ab[(size_t)nd * KQ8 + c]);
            const uint32_t* u = (const uint32_t*)&v;
            float* dst = sA + r * AS + c * 8;
            #pragma unroll
            for (int j = 0; j < 4; j++) {
                float2 fv = unpack_bf2(u[j]);
                dst[2 * j] = fv.x; dst[2 * j + 1] = fv.y;
            }
        }
        __syncthreads();

        uint32_t a[KQ8][4];
        #pragma unroll
        for (int kk = 0; kk < KQ8; kk++) {
            const float* p0 = sA + (mrow + g) * AS + kk * 8 + tg;
            const float* p1 = sA + (mrow + g + 8) * AS + kk * 8 + tg;
            a[kk][0] = __float_as_uint(p0[0]);
            a[kk][1] = __float_as_uint(p1[0]);
            a[kk][2] = __float_as_uint(p0[4]);
            a[kk][3] = __float_as_uint(p1[4]);
        }

        int row0 = node0 + mrow + g;
        int row1 = row0 + 8;
        #pragma unroll 2
        for (int ng = 0; ng < NS / 8; ng++) {
            float d0 = 0.f, d1 = 0.f, d2 = 0.f, d3 = 0.f;
            const float* bp = sB + (ng * 8 + g) * AS + tg;
            #pragma unroll
            for (int kk = 0; kk < KQ8; kk++) {
                uint32_t b0 = __float_as_uint(bp[kk * 8]);
                uint32_t b1 = __float_as_uint(bp[kk * 8 + 4]);
                asm volatile(
                    "mma.sync.aligned.m16n8k8.row.col.f32.tf32.tf32.f32 "
                    "{%0,%1,%2,%3}, {%4,%5,%6,%7}, {%8,%9}, {%0,%1,%2,%3};"
                    : "+f"(d0), "+f"(d1), "+f"(d2), "+f"(d3)
                    : "r"(a[kk][0]), "r"(a[kk][1]), "r"(a[kk][2]), "r"(a[kk][3]),
                      "r"(b0), "r"(b1));
            }
            int col = ng * 8 + 2 * tg;
            float2 bs = __ldg((const float2*)&bias[col]);
            if (row0 < NN)
                *(uint32_t*)(out + (size_t)row0 * NTOT + col) =
                    pack_bf2(fmaxf(d0 + bs.x, 0.f), fmaxf(d1 + bs.y, 0.f));
            if (row1 < NN)
                *(uint32_t*)(out + (size_t)row1 * NTOT + col) =
                    pack_bf2(fmaxf(d2 + bs.x, 0.f), fmaxf(d3 + bs.y, 0.f));
        }
    }
}

// ---------------- mean-pool (bf16 in) + head --------------------------------
__global__ void poolb_kernel(const __nv_bfloat16* __restrict__ h,
                             const int* __restrict__ batch) {
    const int CH = 64;
    int f = threadIdx.x;
    int n0 = blockIdx.x * CH;
    float acc = 0.f;
    int curg = -1;
    for (int i = 0; i < CH; i++) {
        int nd = n0 + i;
        if (nd >= NN) break;
        int g = batch[nd];
        if (g != curg) {
            if (curg >= 0) atomicAdd(&g_pool[curg * 256 + f], acc);
            acc = 0.f; curg = g;
        }
        acc += __bfloat162float(h[(size_t)nd * 256 + f]);
    }
    if (curg >= 0) atomicAdd(&g_pool[curg * 256 + f], acc);
}

__global__ void head_kernel(const float* __restrict__ fcW, const float* __restrict__ fcb,
                            float* __restrict__ out) {
    __shared__ float slog[NG * NC];
    int tid = threadIdx.x;
    if (tid < NG * NC) {
        int g = tid / NC, c = tid % NC;
        float inv = 1.f / fmaxf(g_gcnt[g], 1.f);
        float a = fcb[c];
        for (int k = 0; k < 256; k++)
            a += g_pool[g * 256 + k] * inv * fcW[k * NC + c];
        slog[tid] = a;
    }
    __syncthreads();
    if (tid < NG * NC) {
        int g = tid / NC;
        float m = -1e30f;
        for (int i = 0; i < NC; i++) m = fmaxf(m, slog[g * NC + i]);
        float s = 0.f;
        for (int i = 0; i < NC; i++) s += expf(slog[g * NC + i] - m);
        out[tid] = slog[tid] - m - logf(s);
    }
}

// ---------------- launch -----------------------------------------------------
extern "C" void kernel_launch(void* const* d_in, const int* in_sizes, int n_in,
                              void* d_out, int out_size) {
    const float* x   = (const float*)d_in[0];
    const int*   ei  = (const int*)d_in[1];
    const int*   bat = (const int*)d_in[2];
    const float* W1 = (const float*)d_in[3];
    const float* b1 = (const float*)d_in[4];
    const float* W2 = (const float*)d_in[5];
    const float* b2 = (const float*)d_in[6];
    const float* W3 = (const float*)d_in[7];
    const float* b3 = (const float*)d_in[8];
    const float* W4 = (const float*)d_in[9];
    const float* b4 = (const float*)d_in[10];
    const float* fcW = (const float*)d_in[11];
    const float* fcb = (const float*)d_in[12];
    float* out = (float*)d_out;

    float *Wt1, *Wt2, *Wt3, *Wt4;
    __nv_bfloat16 *zx, *bA, *bB, *hO;
    cudaGetSymbolAddress((void**)&zx, g_zx);
    cudaGetSymbolAddress((void**)&bA, g_b16A);
    cudaGetSymbolAddress((void**)&bB, g_b16B);
    cudaGetSymbolAddress((void**)&hO, g_hO);
    cudaGetSymbolAddress((void**)&Wt1, g_Wt1);
    cudaGetSymbolAddress((void**)&Wt2, g_Wt2);
    cudaGetSymbolAddress((void**)&Wt3, g_Wt3);
    cudaGetSymbolAddress((void**)&Wt4, g_Wt4);

    const int smL1 = (128 * (8 + 4) + 32 * (8 + 4)) * 4;        // 7680
    const int smL2 = (128 * (32 + 4) + 64 * (32 + 4)) * 4;      // 27648
    const int smL3 = (128 * (64 + 4) + 128 * (64 + 4)) * 4;     // 69632
    const int smL4 = (128 * (128 + 4) + 256 * (128 + 4)) * 4;   // 202752
    cudaFuncSetAttribute(mma_kernel<64, 128, 1>,
                         cudaFuncAttributeMaxDynamicSharedMemorySize, smL3);
    cudaFuncSetAttribute(mma_l4_kernel,
                         cudaFuncAttributeMaxDynamicSharedMemorySize, smL4);

    const int EB = (NE + 255) / 256;
    const int NB = (NN + 255) / 256;

    init_kernel<<<NB, 256>>>(W1, W2, W3, W4);
    count_kernel<<<EB, 256>>>(ei);
    chunkred_kernel<<<NCHUNK, 256>>>();
    scan2_kernel<<<NCHUNK, 1024>>>(x);
    fillg_kernel<<<EB, 256>>>(ei, bat);

    // layer 1: agg1(zx)[8] -> bB; mma K=8 -> bA z1 [NN][32]
    agg1_kernel<<<NB, 256>>>((const uint4*)zx, (uint4*)bB);
    mma_kernel<8, 32, 1><<<dim3(391, 1), 256, smL1>>>(bB, Wt1, b1, bA);
    // layer 2: aggb(bA)[32] -> bB; mma K=32 -> bA z2 [NN][64]
    {
        dim3 blk(4, 64);
        aggb_kernel<32><<<(NN + 63) / 64, blk>>>((const uint4*)bA, (uint4*)bB);
        mma_kernel<32, 64, 1><<<dim3(391, 1), 256, smL2>>>(bB, Wt2, b2, bA);
    }
    // layer 3: aggb(bA)[64] -> bB; mma K=64 -> bA z3 [NN][128]
    {
        dim3 blk(8, 32);
        aggb_kernel<64><<<(NN + 31) / 32, blk>>>((const uint4*)bA, (uint4*)bB);
        mma_kernel<64, 128, 1><<<dim3(391, 1), 256, smL3>>>(bB, Wt3, b3, bA);
    }
    // layer 4: aggb(bA)[128] -> bB; persistent mma -> hO h4 [NN][256]
    {
        dim3 blk(16, 16);
        aggb_kernel<128><<<(NN + 15) / 16, blk>>>((const uint4*)bA, (uint4*)bB);
        mma_l4_kernel<<<148, 256, smL4>>>(bB, Wt4, b4, hO);
    }

    // mean pool + head
    poolb_kernel<<<(NN + 63) / 64, 256>>>(hO, bat);
    head_kernel<<<1, 640>>>(fcW, fcb, out);

    (void)in_sizes; (void)n_in; (void)out_size;
}

// round 13
// speedup vs baseline: 1.3136x; 1.0228x over previous
#include <cuda_runtime.h>
#include <cuda_bf16.h>
#include <math.h>
#include <stdint.h>

#define NN 50000
#define NE 800000
#define NG 64
#define NC 10
#define CHUNK 1024
#define NCHUNK ((NN + CHUNK - 1) / CHUNK)   // 49

__device__ __forceinline__ uint32_t f2tf32(float x) {
    uint32_t u;
    asm("cvt.rna.tf32.f32 %0, %1;" : "=r"(u) : "f"(x));
    return u;
}
__device__ __forceinline__ uint32_t pack_bf2(float a, float b) {
    __nv_bfloat162 p = __floats2bfloat162_rn(a, b);
    return *(uint32_t*)&p;
}
__device__ __forceinline__ float2 unpack_bf2(uint32_t u) {
    return __bfloat1622float2(*(__nv_bfloat162*)&u);
}

// ---------------- scratch ----------------------------------------------------
__device__ __align__(16) float g_dinv[NN];
__device__ int   g_cnt[NN];
__device__ int   g_rowptr[NN + 1];
__device__ int   g_cursor[NN];
__device__ __align__(16) unsigned short g_col[NE];
__device__ __align__(16) __nv_bfloat16 g_zx[NN * 8];
__device__ __align__(16) __nv_bfloat16 g_b16A[NN * 128];
__device__ __align__(16) __nv_bfloat16 g_b16B[NN * 128];
__device__ __align__(16) __nv_bfloat16 g_hO[NN * 256];
__device__ __align__(16) float g_Wt1[32 * 8];
__device__ __align__(16) float g_Wt2[64 * 32];
__device__ __align__(16) float g_Wt3[128 * 64];
__device__ __align__(16) float g_Wt4[256 * 128];
__device__ float g_pool[NG * 256];
__device__ float g_gcnt[NG];

// ---------------- preprocessing ---------------------------------------------
__global__ void init_kernel(const float* __restrict__ W1, const float* __restrict__ W2,
                            const float* __restrict__ W3, const float* __restrict__ W4) {
    int i = blockIdx.x * blockDim.x + threadIdx.x;
    if (i < NN) g_cnt[i] = 0;
    if (i < NG * 256) g_pool[i] = 0.f;
    if (i < NG) g_gcnt[i] = 0.f;
    if (i < 32 * 8) {
        int n = i >> 3, k = i & 7;
        g_Wt1[i] = (k < 5) ? __uint_as_float(f2tf32(W1[k * 32 + n])) : 0.f;
    }
    if (i < 64 * 32) {
        int n = i >> 5, k = i & 31;
        g_Wt2[i] = __uint_as_float(f2tf32(W2[k * 64 + n]));
    }
    if (i < 128 * 64) {
        int n = i >> 6, k = i & 63;
        g_Wt3[i] = __uint_as_float(f2tf32(W3[k * 128 + n]));
    }
    if (i < 256 * 128) {
        int n = i >> 7, k = i & 127;
        g_Wt4[i] = __uint_as_float(f2tf32(W4[k * 256 + n]));
    }
}

__global__ void count_kernel(const int* __restrict__ ei) {
    int e = blockIdx.x * blockDim.x + threadIdx.x;
    if (e < NE) atomicAdd(&g_cnt[ei[NE + e]], 1);
}

// single merged scan: base from direct re-reduction, own-chunk scan, dinv, zx
__global__ void scanall_kernel(const float* __restrict__ x) {
    __shared__ int wsum[32];
    __shared__ int warpsum[32];
    __shared__ int base_s;
    int c = blockIdx.x, tid = threadIdx.x;
    int lane = tid & 31, w = tid >> 5;

    // base = sum of g_cnt[0 .. c*CHUNK)
    int p = 0;
    for (int idx = tid; idx < c * CHUNK; idx += CHUNK) p += g_cnt[idx];
    for (int off = 16; off; off >>= 1) p += __shfl_down_sync(~0u, p, off);
    if (lane == 0) wsum[w] = p;
    __syncthreads();
    if (w == 0) {
        int t = wsum[lane];
        for (int off = 16; off; off >>= 1) t += __shfl_down_sync(~0u, t, off);
        if (lane == 0) base_s = t;
    }
    __syncthreads();

    int i = c * CHUNK + tid;
    int v = (i < NN) ? g_cnt[i] : 0;
    float dv = rsqrtf((float)(v + 1));
    if (i < NN) g_dinv[i] = dv;

    int incl = v;
    for (int off = 1; off < 32; off <<= 1) {
        int t = __shfl_up_sync(~0u, incl, off);
        if (lane >= off) incl += t;
    }
    if (lane == 31) warpsum[w] = incl;
    __syncthreads();
    if (w == 0) {
        int ws = warpsum[lane];
        for (int off = 1; off < 32; off <<= 1) {
            int t = __shfl_up_sync(~0u, ws, off);
            if (lane >= off) ws += t;
        }
        warpsum[lane] = ws;
    }
    __syncthreads();
    int excl = incl - v + (w > 0 ? warpsum[w - 1] : 0) + base_s;
    if (i < NN) {
        g_rowptr[i] = excl; g_cursor[i] = excl;
        float v0 = x[(size_t)i * 5 + 0], v1 = x[(size_t)i * 5 + 1];
        float v2 = x[(size_t)i * 5 + 2], v3 = x[(size_t)i * 5 + 3];
        float v4 = x[(size_t)i * 5 + 4];
        uint4 pk;
        pk.x = pack_bf2(dv * v0, dv * v1);
        pk.y = pack_bf2(dv * v2, dv * v3);
        pk.z = pack_bf2(dv * v4, 0.f);
        pk.w = 0u;
        *(uint4*)(g_zx + (size_t)i * 8) = pk;
    }
    if (i == NN - 1) g_rowptr[NN] = excl + v;
}

__global__ void fillg_kernel(const int* __restrict__ ei, const int* __restrict__ bat) {
    int e = blockIdx.x * blockDim.x + threadIdx.x;
    if (e < NE) {
        int s = ei[e];
        int d = ei[NE + e];
        int pos = atomicAdd(&g_cursor[d], 1);
        g_col[pos] = (unsigned short)s;
    }
    if (e < NN) atomicAdd(&g_gcnt[bat[e]], 1.f);
}

// ---------------- shared mma compute body ------------------------------------
// sA [128][K+4] f32, sB [NS][K+4] f32 already staged; computes 128xNS tile.
template <int K, int NS, int NTOT, int SCALE>
__device__ __forceinline__ void mma_compute(
    const float* sA, const float* sB, int tid, int node0, int n0,
    const float* __restrict__ bias, __nv_bfloat16* __restrict__ out)
{
    constexpr int AS = K + 4;
    constexpr int KQ8 = K / 8;
    int warp = tid >> 5, lane = tid & 31;
    int g = lane >> 2, tg = lane & 3;
    int mrow = warp * 16;

    uint32_t a[KQ8][4];
    #pragma unroll
    for (int kk = 0; kk < KQ8; kk++) {
        const float* p0 = sA + (mrow + g) * AS + kk * 8 + tg;
        const float* p1 = sA + (mrow + g + 8) * AS + kk * 8 + tg;
        a[kk][0] = __float_as_uint(p0[0]);
        a[kk][1] = __float_as_uint(p1[0]);
        a[kk][2] = __float_as_uint(p0[4]);
        a[kk][3] = __float_as_uint(p1[4]);
    }

    int row0 = node0 + mrow + g;
    int row1 = row0 + 8;
    float sc0 = 1.f, sc1 = 1.f;
    if (SCALE) {
        if (row0 < NN) sc0 = __ldg(&g_dinv[row0]);
        if (row1 < NN) sc1 = __ldg(&g_dinv[row1]);
    }
    #pragma unroll 2
    for (int ng = 0; ng < NS / 8; ng++) {
        float d0 = 0.f, d1 = 0.f, d2 = 0.f, d3 = 0.f;
        const float* bp = sB + (ng * 8 + g) * AS + tg;
        #pragma unroll
        for (int kk = 0; kk < KQ8; kk++) {
            uint32_t b0 = __float_as_uint(bp[kk * 8]);
            uint32_t b1 = __float_as_uint(bp[kk * 8 + 4]);
            asm volatile(
                "mma.sync.aligned.m16n8k8.row.col.f32.tf32.tf32.f32 "
                "{%0,%1,%2,%3}, {%4,%5,%6,%7}, {%8,%9}, {%0,%1,%2,%3};"
                : "+f"(d0), "+f"(d1), "+f"(d2), "+f"(d3)
                : "r"(a[kk][0]), "r"(a[kk][1]), "r"(a[kk][2]), "r"(a[kk][3]),
                  "r"(b0), "r"(b1));
        }
        int col = n0 + ng * 8 + 2 * tg;
        float2 bs = __ldg((const float2*)&bias[col]);
        if (row0 < NN)
            *(uint32_t*)(out + (size_t)row0 * NTOT + col) =
                pack_bf2(fmaxf(d0 + bs.x, 0.f) * sc0, fmaxf(d1 + bs.y, 0.f) * sc0);
        if (row1 < NN)
            *(uint32_t*)(out + (size_t)row1 * NTOT + col) =
                pack_bf2(fmaxf(d2 + bs.x, 0.f) * sc1, fmaxf(d3 + bs.y, 0.f) * sc1);
    }
}

// ---------------- layer 1: fused agg(zx) + mma K=8 -> z1 [NN][32] -----------
__global__ __launch_bounds__(256) void mma1_kernel(
    const uint4* __restrict__ z, const float* __restrict__ Wt,
    const float* __restrict__ bias, __nv_bfloat16* __restrict__ out)
{
    constexpr int K = 8, NS = 32, AS = K + 4;
    extern __shared__ float smem[];
    float* sA = smem;             // [128][12]
    float* sB = smem + 128 * AS;  // [32][12]
    int tid = threadIdx.x;
    int node0 = blockIdx.x * 128;

    // gather: 2 threads per node, split edge chain, shfl-combine
    {
        int r = tid >> 1, h = tid & 1;
        int nd = node0 + r;
        float acc[8] = {0, 0, 0, 0, 0, 0, 0, 0};
        if (nd < NN) {
            int e0 = g_rowptr[nd], end = g_rowptr[nd + 1];
            if (h == 0) {
                uint4 v = __ldg(&z[nd]);
                const uint32_t* u = (const uint32_t*)&v;
                #pragma unroll
                for (int j = 0; j < 4; j++) {
                    float2 fv = unpack_bf2(u[j]);
                    acc[2 * j] = fv.x; acc[2 * j + 1] = fv.y;
                }
            }
            int e = e0 + h;
            for (; e + 2 < end; e += 4) {
                int c0 = __ldg(&g_col[e]), c1 = __ldg(&g_col[e + 2]);
                uint4 v0 = __ldg(&z[c0]), v1 = __ldg(&z[c1]);
                const uint32_t* u0 = (const uint32_t*)&v0;
                const uint32_t* u1 = (const uint32_t*)&v1;
                #pragma unroll
                for (int j = 0; j < 4; j++) {
                    float2 f0 = unpack_bf2(u0[j]), f1 = unpack_bf2(u1[j]);
                    acc[2 * j]     += f0.x + f1.x;
                    acc[2 * j + 1] += f0.y + f1.y;
                }
            }
            if (e < end) {
                uint4 v0 = __ldg(&z[__ldg(&g_col[e])]);
                const uint32_t* u0 = (const uint32_t*)&v0;
                #pragma unroll
                for (int j = 0; j < 4; j++) {
                    float2 f0 = unpack_bf2(u0[j]);
                    acc[2 * j] += f0.x; acc[2 * j + 1] += f0.y;
                }
            }
        }
        #pragma unroll
        for (int j = 0; j < 8; j++)
            acc[j] += __shfl_down_sync(~0u, acc[j], 1);
        if (h == 0) {
            float dv = (nd < NN) ? g_dinv[nd] : 0.f;
            float* dst = sA + r * AS;
            #pragma unroll
            for (int j = 0; j < 8; j++) dst[j] = dv * acc[j];
        }
    }
    if (tid < 64) {  // B: 32 rows x 2 float4
        int r = tid >> 1, kq = tid & 1;
        float4 v = __ldg((const float4*)Wt + r * 2 + kq);
        *(float4*)(sB + r * AS + kq * 4) = v;
    }
    __syncthreads();
    mma_compute<8, 32, 32, 1>(sA, sB, tid, node0, 0, bias, out);
}

// ---------------- layer 2: fused agg(z1) + mma K=32 -> z2 [NN][64] ----------
__global__ __launch_bounds__(256) void mma2_kernel(
    const uint4* __restrict__ z, const float* __restrict__ Wt,
    const float* __restrict__ bias, __nv_bfloat16* __restrict__ out)
{
    constexpr int K = 32, NS = 64, AS = K + 4;
    extern __shared__ float smem[];
    float* sA = smem;             // [128][36]
    float* sB = smem + 128 * AS;  // [64][36]
    int tid = threadIdx.x;
    int node0 = blockIdx.x * 128;

    for (int t = tid; t < 128 * 4; t += 256) {
        int r = t >> 2, c = t & 3;
        int nd = node0 + r;
        float acc[8] = {0, 0, 0, 0, 0, 0, 0, 0};
        float dv = 0.f;
        if (nd < NN) {
            dv = g_dinv[nd];
            uint4 v = __ldg(&z[(size_t)nd * 4 + c]);
            const uint32_t* u = (const uint32_t*)&v;
            #pragma unroll
            for (int j = 0; j < 4; j++) {
                float2 fv = unpack_bf2(u[j]);
                acc[2 * j] = fv.x; acc[2 * j + 1] = fv.y;
            }
            int e = g_rowptr[nd], end = g_rowptr[nd + 1];
            for (; e + 3 < end; e += 4) {
                int c0 = __ldg(&g_col[e]),     c1 = __ldg(&g_col[e + 1]);
                int c2 = __ldg(&g_col[e + 2]), c3 = __ldg(&g_col[e + 3]);
                uint4 v0 = __ldg(&z[(size_t)c0 * 4 + c]);
                uint4 v1 = __ldg(&z[(size_t)c1 * 4 + c]);
                uint4 v2 = __ldg(&z[(size_t)c2 * 4 + c]);
                uint4 v3 = __ldg(&z[(size_t)c3 * 4 + c]);
                const uint32_t* u0 = (const uint32_t*)&v0;
                const uint32_t* u1 = (const uint32_t*)&v1;
                const uint32_t* u2 = (const uint32_t*)&v2;
                const uint32_t* u3 = (const uint32_t*)&v3;
                #pragma unroll
                for (int j = 0; j < 4; j++) {
                    float2 f0 = unpack_bf2(u0[j]), f1 = unpack_bf2(u1[j]);
                    float2 f2 = unpack_bf2(u2[j]), f3 = unpack_bf2(u3[j]);
                    acc[2 * j]     += f0.x + f1.x + f2.x + f3.x;
                    acc[2 * j + 1] += f0.y + f1.y + f2.y + f3.y;
                }
            }
            for (; e < end; e++) {
                uint4 v0 = __ldg(&z[(size_t)__ldg(&g_col[e]) * 4 + c]);
                const uint32_t* u0 = (const uint32_t*)&v0;
                #pragma unroll
                for (int j = 0; j < 4; j++) {
                    float2 f0 = unpack_bf2(u0[j]);
                    acc[2 * j] += f0.x; acc[2 * j + 1] += f0.y;
                }
            }
        }
        float* dst = sA + r * AS + c * 8;
        #pragma unroll
        for (int j = 0; j < 8; j++) dst[j] = dv * acc[j];
    }
    for (int t = tid; t < 64 * 8; t += 256) {  // B: 64 rows x 8 float4
        int r = t >> 3, kq = t & 7;
        float4 v = __ldg((const float4*)Wt + (size_t)r * 8 + kq);
        *(float4*)(sB + r * AS + kq * 4) = v;
    }
    __syncthreads();
    mma_compute<32, 64, 64, 1>(sA, sB, tid, node0, 0, bias, out);
}

// ---------------- standalone agg (layers 3-4) --------------------------------
template <int F>
__global__ void aggb_kernel(const uint4* __restrict__ z, uint4* __restrict__ out) {
    constexpr int FQ8 = F / 8;
    int node = blockIdx.x * blockDim.y + threadIdx.y;
    if (node >= NN) return;
    int f = threadIdx.x;
    float acc[8];
    {
        uint4 v = __ldg(&z[(size_t)node * FQ8 + f]);
        const uint32_t* u = (const uint32_t*)&v;
        #pragma unroll
        for (int j = 0; j < 4; j++) {
            float2 fv = unpack_bf2(u[j]);
            acc[2 * j] = fv.x; acc[2 * j + 1] = fv.y;
        }
    }
    int e = g_rowptr[node], end = g_rowptr[node + 1];
    for (; e + 3 < end; e += 4) {
        int c0 = __ldg(&g_col[e]),     c1 = __ldg(&g_col[e + 1]);
        int c2 = __ldg(&g_col[e + 2]), c3 = __ldg(&g_col[e + 3]);
        uint4 v0 = __ldg(&z[(size_t)c0 * FQ8 + f]);
        uint4 v1 = __ldg(&z[(size_t)c1 * FQ8 + f]);
        uint4 v2 = __ldg(&z[(size_t)c2 * FQ8 + f]);
        uint4 v3 = __ldg(&z[(size_t)c3 * FQ8 + f]);
        const uint32_t* u0 = (const uint32_t*)&v0;
        const uint32_t* u1 = (const uint32_t*)&v1;
        const uint32_t* u2 = (const uint32_t*)&v2;
        const uint32_t* u3 = (const uint32_t*)&v3;
        #pragma unroll
        for (int j = 0; j < 4; j++) {
            float2 f0 = unpack_bf2(u0[j]), f1 = unpack_bf2(u1[j]);
            float2 f2 = unpack_bf2(u2[j]), f3 = unpack_bf2(u3[j]);
            acc[2 * j]     += f0.x + f1.x + f2.x + f3.x;
            acc[2 * j + 1] += f0.y + f1.y + f2.y + f3.y;
        }
    }
    for (; e < end; e++) {
        uint4 v0 = __ldg(&z[(size_t)__ldg(&g_col[e]) * FQ8 + f]);
        const uint32_t* u0 = (const uint32_t*)&v0;
        #pragma unroll
        for (int j = 0; j < 4; j++) {
            float2 f0 = unpack_bf2(u0[j]);
            acc[2 * j] += f0.x; acc[2 * j + 1] += f0.y;
        }
    }
    float dv = g_dinv[node];
    uint32_t pk[4];
    #pragma unroll
    for (int j = 0; j < 4; j++) pk[j] = pack_bf2(dv * acc[2 * j], dv * acc[2 * j + 1]);
    out[(size_t)node * FQ8 + f] = *(uint4*)pk;
}

// ---------------- layer 3 tiled mma (K=64, N=128) ----------------------------
__global__ __launch_bounds__(256) void mma3_kernel(
    const __nv_bfloat16* __restrict__ A, const float* __restrict__ Wt,
    const float* __restrict__ bias, __nv_bfloat16* __restrict__ out)
{
    constexpr int K = 64, NS = 128, AS = K + 4;
    constexpr int KQ = K / 4, KQ8 = K / 8;
    extern __shared__ float smem[];
    float* sA = smem;
    float* sB = smem + 128 * AS;
    int tid = threadIdx.x;
    int node0 = blockIdx.x * 128;

    const uint4* Ab = (const uint4*)A;
    for (int i = tid; i < 128 * KQ8; i += 256) {
        int r = i / KQ8, c = i - r * KQ8;
        int nd = node0 + r;
        uint4 v = make_uint4(0, 0, 0, 0);
        if (nd < NN) v = __ldg(&Ab[(size_t)nd * KQ8 + c]);
        const uint32_t* u = (const uint32_t*)&v;
        float* dst = sA + r * AS + c * 8;
        #pragma unroll
        for (int j = 0; j < 4; j++) {
            float2 fv = unpack_bf2(u[j]);
            dst[2 * j] = fv.x; dst[2 * j + 1] = fv.y;
        }
    }
    for (int i = tid; i < NS * KQ; i += 256) {
        int r = i / KQ, kq = i - r * KQ;
        float4 v = __ldg((const float4*)Wt + (size_t)r * KQ + kq);
        *(float4*)(sB + r * AS + kq * 4) = v;
    }
    __syncthreads();
    mma_compute<64, 128, 128, 1>(sA, sB, tid, node0, 0, bias, out);
}

// ---------------- persistent layer 4 mma (K=128, N=256) ----------------------
__global__ __launch_bounds__(256) void mma_l4_kernel(
    const __nv_bfloat16* __restrict__ A, const float* __restrict__ Wt,
    const float* __restrict__ bias, __nv_bfloat16* __restrict__ out)
{
    constexpr int K = 128, NS = 256, AS = K + 4;
    constexpr int KQ = K / 4, KQ8 = K / 8;
    constexpr int NTILES = (NN + 127) / 128;
    extern __shared__ float smem[];
    float* sA = smem;
    float* sB = smem + 128 * AS;
    int tid = threadIdx.x;

    for (int i = tid; i < NS * KQ; i += 256) {
        int r = i / KQ, kq = i - r * KQ;
        float4 v = __ldg((const float4*)Wt + (size_t)r * KQ + kq);
        *(float4*)(sB + r * AS + kq * 4) = v;
    }
    const uint4* Ab = (const uint4*)A;

    for (int tile = blockIdx.x; tile < NTILES; tile += gridDim.x) {
        int node0 = tile * 128;
        __syncthreads();
        for (int i = tid; i < 128 * KQ8; i += 256) {
            int r = i / KQ8, c = i - r * KQ8;
            int nd = node0 + r;
            uint4 v = make_uint4(0, 0, 0, 0);
            if (nd < NN) v = __ldg(&Ab[(size_t)nd * KQ8 + c]);
            const uint32_t* u = (const uint32_t*)&v;
            float* dst = sA + r * AS + c * 8;
            #pragma unroll
            for (int j = 0; j < 4; j++) {
                float2 fv = unpack_bf2(u[j]);
                dst[2 * j] = fv.x; dst[2 * j + 1] = fv.y;
            }
        }
        __syncthreads();
        mma_compute<128, 256, 256, 0>(sA, sB, tid, node0, 0, bias, out);
    }
}

// ---------------- mean-pool + head -------------------------------------------
__global__ void poolb_kernel(const __nv_bfloat16* __restrict__ h,
                             const int* __restrict__ batch) {
    const int CH = 64;
    int f = threadIdx.x;
    int n0 = blockIdx.x * CH;
    float acc = 0.f;
    int curg = -1;
    for (int i = 0; i < CH; i++) {
        int nd = n0 + i;
        if (nd >= NN) break;
        int g = batch[nd];
        if (g != curg) {
            if (curg >= 0) atomicAdd(&g_pool[curg * 256 + f], acc);
            acc = 0.f; curg = g;
        }
        acc += __bfloat162float(h[(size_t)nd * 256 + f]);
    }
    if (curg >= 0) atomicAdd(&g_pool[curg * 256 + f], acc);
}

__global__ void head_kernel(const float* __restrict__ fcW, const float* __restrict__ fcb,
                            float* __restrict__ out) {
    __shared__ float slog[NG * NC];
    int tid = threadIdx.x;
    if (tid < NG * NC) {
        int g = tid / NC, c = tid % NC;
        float inv = 1.f / fmaxf(g_gcnt[g], 1.f);
        float a = fcb[c];
        for (int k = 0; k < 256; k++)
            a += g_pool[g * 256 + k] * inv * fcW[k * NC + c];
        slog[tid] = a;
    }
    __syncthreads();
    if (tid < NG * NC) {
        int g = tid / NC;
        float m = -1e30f;
        for (int i = 0; i < NC; i++) m = fmaxf(m, slog[g * NC + i]);
        float s = 0.f;
        for (int i = 0; i < NC; i++) s += expf(slog[g * NC + i] - m);
        out[tid] = slog[tid] - m - logf(s);
    }
}

// ---------------- launch -----------------------------------------------------
extern "C" void kernel_launch(void* const* d_in, const int* in_sizes, int n_in,
                              void* d_out, int out_size) {
    const float* x   = (const float*)d_in[0];
    const int*   ei  = (const int*)d_in[1];
    const int*   bat = (const int*)d_in[2];
    const float* W1 = (const float*)d_in[3];
    const float* b1 = (const float*)d_in[4];
    const float* W2 = (const float*)d_in[5];
    const float* b2 = (const float*)d_in[6];
    const float* W3 = (const float*)d_in[7];
    const float* b3 = (const float*)d_in[8];
    const float* W4 = (const float*)d_in[9];
    const float* b4 = (const float*)d_in[10];
    const float* fcW = (const float*)d_in[11];
    const float* fcb = (const float*)d_in[12];
    float* out = (float*)d_out;

    float *Wt1, *Wt2, *Wt3, *Wt4;
    __nv_bfloat16 *zx, *bA, *bB, *hO;
    cudaGetSymbolAddress((void**)&zx, g_zx);
    cudaGetSymbolAddress((void**)&bA, g_b16A);
    cudaGetSymbolAddress((void**)&bB, g_b16B);
    cudaGetSymbolAddress((void**)&hO, g_hO);
    cudaGetSymbolAddress((void**)&Wt1, g_Wt1);
    cudaGetSymbolAddress((void**)&Wt2, g_Wt2);
    cudaGetSymbolAddress((void**)&Wt3, g_Wt3);
    cudaGetSymbolAddress((void**)&Wt4, g_Wt4);

    const int sm1  = (128 * 12 + 32 * 12) * 4;                  // 7680
    const int sm2  = (128 * 36 + 64 * 36) * 4;                  // 27648
    const int smL3 = (128 * 68 + 128 * 68) * 4;                 // 69632
    const int smL4 = (128 * 132 + 256 * 132) * 4;               // 202752
    cudaFuncSetAttribute(mma3_kernel,
                         cudaFuncAttributeMaxDynamicSharedMemorySize, smL3);
    cudaFuncSetAttribute(mma_l4_kernel,
                         cudaFuncAttributeMaxDynamicSharedMemorySize, smL4);

    const int EB = (NE + 255) / 256;
    const int NB = (NN + 255) / 256;

    init_kernel<<<NB, 256>>>(W1, W2, W3, W4);
    count_kernel<<<EB, 256>>>(ei);
    scanall_kernel<<<NCHUNK, 1024>>>(x);
    fillg_kernel<<<EB, 256>>>(ei, bat);

    // layer 1 (fused agg+mma): zx -> bA z1 [NN][32]
    mma1_kernel<<<391, 256, sm1>>>((const uint4*)zx, Wt1, b1, bA);
    // layer 2 (fused agg+mma): bA -> bB z2 [NN][64]
    mma2_kernel<<<391, 256, sm2>>>((const uint4*)bA, Wt2, b2, bB);
    // layer 3: agg(bB)[64] -> bA; mma -> bB z3 [NN][128]
    {
        dim3 blk(8, 32);
        aggb_kernel<64><<<(NN + 31) / 32, blk>>>((const uint4*)bB, (uint4*)bA);
        mma3_kernel<<<391, 256, smL3>>>(bA, Wt3, b3, bB);
    }
    // layer 4: agg(bB)[128] -> bA; persistent mma -> hO [NN][256]
    {
        dim3 blk(16, 16);
        aggb_kernel<128><<<(NN + 15) / 16, blk>>>((const uint4*)bB, (uint4*)bA);
        mma_l4_kernel<<<148, 256, smL4>>>(bA, Wt4, b4, hO);
    }

    poolb_kernel<<<(NN + 63) / 64, 256>>>(hO, bat);
    head_kernel<<<1, 640>>>(fcW, fcb, out);

    (void)in_sizes; (void)n_in; (void)out_size;
}